// round 1
// baseline (speedup 1.0000x reference)
#include <cuda_runtime.h>
#include <math.h>
#include <stdint.h>

#define DIMM 768
#define DIN_ 1024
#define NQ_ 384
#define NB_ 12
#define BATCH_ 2
#define LSEQ_ 1024
#define DI_ 1536
#define DS_ 16
#define DC_ 4
#define DTR_ 48
#define NH_ 16
#define HD_ 48
#define NM_ 14

// ---------------- arena ----------------
// all sizes in floats
#define SZ_BL_DIM   (BATCH_*LSEQ_*DIMM)      // 1572864
#define SZ_XZ       (BATCH_*LSEQ_*2*DI_)     // 6291456
#define SZ_XC       (BATCH_*LSEQ_*DI_)       // 3145728
#define SZ_DBL      (BATCH_*LSEQ_*80)        // 163840
#define SZ_Q_DIM    (BATCH_*NQ_*DIMM)        // 589824
#define SZ_CAT      (BATCH_*NQ_*2*DIMM)      // 1179648

#define OFF_FEATS  ((size_t)0)
#define OFF_FWD    (OFF_FEATS + SZ_BL_DIM)
#define OFF_FLIP   (OFF_FWD   + SZ_BL_DIM)
#define OFF_C      (OFF_FLIP  + SZ_BL_DIM)
#define OFF_MO     (OFF_C     + SZ_BL_DIM)
#define OFF_XZ     (OFF_MO    + SZ_BL_DIM)
#define OFF_XCB    (OFF_XZ    + SZ_XZ)
#define OFF_DBL    (OFF_XCB   + SZ_XC)
#define OFF_DT     (OFF_DBL   + SZ_DBL)
#define OFF_YS     (OFF_DT    + SZ_XC)
#define OFF_X      (OFF_YS    + SZ_XC)
#define OFF_XN     (OFF_X     + SZ_Q_DIM)
#define OFF_QB     (OFF_XN    + SZ_Q_DIM)
#define OFF_KB     (OFF_QB    + SZ_Q_DIM)
#define OFF_VB     (OFF_KB    + SZ_BL_DIM)
#define OFF_OB     (OFF_VB    + SZ_BL_DIM)
#define OFF_SCORE  (OFF_OB    + SZ_Q_DIM)
#define OFF_CAT    (OFF_SCORE + SZ_Q_DIM)
#define ARENA_SZ   (OFF_CAT   + SZ_CAT)

__device__ __align__(256) float g_arena[ARENA_SZ];

// ---------------- helpers ----------------
__device__ __forceinline__ float softplusf(float x) {
    return fmaxf(x, 0.f) + log1pf(expf(-fabsf(x)));
}
__device__ __forceinline__ float siluf(float x) {
    return x / (1.f + expf(-x));
}

// ---------------- generic SGEMM: C = act(A @ B^T + bias) + addend ----------------
// A: (M,K) row stride lda; B: (N,K) row stride ldb; C: (M,N) row stride ldc
__global__ void gemm_kernel(const float* __restrict__ A, int lda,
                            const float* __restrict__ B, int ldb,
                            const float* __restrict__ bias,
                            const float* __restrict__ addend, int ldadd,
                            float* __restrict__ C, int ldc,
                            int M, int N, int K, int act)
{
    __shared__ __align__(16) float As[16][64];
    __shared__ __align__(16) float Bs[16][64];
    int tid = threadIdx.x;
    int tx = tid & 15, ty = tid >> 4;
    int bm = blockIdx.y * 64, bn = blockIdx.x * 64;

    float acc[4][4];
#pragma unroll
    for (int i = 0; i < 4; i++)
#pragma unroll
        for (int j = 0; j < 4; j++) acc[i][j] = 0.f;

    for (int k0 = 0; k0 < K; k0 += 16) {
#pragma unroll
        for (int r = 0; r < 4; r++) {
            int i = tid + r * 256;
            int m = i >> 4, kk = i & 15;
            int gm = bm + m, gk = k0 + kk;
            As[kk][m] = (gm < M && gk < K) ? A[(size_t)gm * lda + gk] : 0.f;
        }
#pragma unroll
        for (int r = 0; r < 4; r++) {
            int i = tid + r * 256;
            int n = i >> 4, kk = i & 15;
            int gn = bn + n, gk = k0 + kk;
            Bs[kk][n] = (gn < N && gk < K) ? B[(size_t)gn * ldb + gk] : 0.f;
        }
        __syncthreads();
#pragma unroll
        for (int kk = 0; kk < 16; kk++) {
            float4 a4 = *reinterpret_cast<const float4*>(&As[kk][ty * 4]);
            float4 b4 = *reinterpret_cast<const float4*>(&Bs[kk][tx * 4]);
            float a[4] = {a4.x, a4.y, a4.z, a4.w};
            float bb[4] = {b4.x, b4.y, b4.z, b4.w};
#pragma unroll
            for (int i = 0; i < 4; i++)
#pragma unroll
                for (int j = 0; j < 4; j++) acc[i][j] += a[i] * bb[j];
        }
        __syncthreads();
    }

#pragma unroll
    for (int i = 0; i < 4; i++) {
        int m = bm + ty * 4 + i;
        if (m >= M) continue;
#pragma unroll
        for (int j = 0; j < 4; j++) {
            int n = bn + tx * 4 + j;
            if (n >= N) continue;
            float v = acc[i][j];
            if (bias) v += bias[n];
            if (act == 1) v = softplusf(v);
            if (addend) v += addend[(size_t)m * ldadd + n];
            C[(size_t)m * ldc + n] = v;
        }
    }
}

static inline void gemm(const float* A, int lda, const float* B, int ldb,
                        const float* bias, const float* addend, int ldadd,
                        float* C, int ldc, int M, int N, int K, int act)
{
    dim3 grid((N + 63) / 64, (M + 63) / 64);
    gemm_kernel<<<grid, 256>>>(A, lda, B, ldb, bias, addend, ldadd, C, ldc, M, N, K, act);
}

// ---------------- layernorm (per row of DIMM) ----------------
__global__ void ln_kernel(const float* __restrict__ x, const float* __restrict__ g,
                          const float* __restrict__ b, float* __restrict__ y)
{
    int r = blockIdx.x;
    const float* xp = x + (size_t)r * DIMM;
    float s = 0.f, ss = 0.f;
    for (int i = threadIdx.x; i < DIMM; i += blockDim.x) {
        float v = xp[i]; s += v; ss += v * v;
    }
    __shared__ float shs[8], shss[8];
    for (int o = 16; o > 0; o >>= 1) {
        s += __shfl_xor_sync(0xffffffffu, s, o);
        ss += __shfl_xor_sync(0xffffffffu, ss, o);
    }
    int w = threadIdx.x >> 5;
    if ((threadIdx.x & 31) == 0) { shs[w] = s; shss[w] = ss; }
    __syncthreads();
    if (threadIdx.x == 0) {
        float ts = 0.f, tss = 0.f;
        int nw = blockDim.x >> 5;
        for (int i = 0; i < nw; i++) { ts += shs[i]; tss += shss[i]; }
        shs[0] = ts; shss[0] = tss;
    }
    __syncthreads();
    float mean = shs[0] / (float)DIMM;
    float var = shss[0] / (float)DIMM - mean * mean;
    float inv = rsqrtf(var + 1e-5f);
    float* yp = y + (size_t)r * DIMM;
    for (int i = threadIdx.x; i < DIMM; i += blockDim.x)
        yp[i] = (xp[i] - mean) * inv * g[i] + b[i];
}

// ---------------- depthwise causal conv + silu ----------------
// xi = xz[..., :DI] (row stride 2*DI). xc out (B,L,DI) contiguous.
__global__ void conv_kernel(const float* __restrict__ xz, const float* __restrict__ cw,
                            const float* __restrict__ cb, float* __restrict__ xc, int L)
{
    int idx = blockIdx.x * blockDim.x + threadIdx.x;
    int total = BATCH_ * L * DI_;
    if (idx >= total) return;
    int d = idx % DI_;
    int l = (idx / DI_) % L;
    int b = idx / (DI_ * L);
    float sum = cb[d];
    const float* base = xz + ((size_t)b * L) * (2 * DI_) + d;
#pragma unroll
    for (int j = 0; j < DC_; j++) {
        int lt = l - (DC_ - 1) + j;
        if (lt >= 0) sum += base[(size_t)lt * (2 * DI_)] * cw[d * DC_ + j];
    }
    xc[idx] = siluf(sum);
}

// ---------------- selective scan + C-contraction + D skip + silu(z) gate ----------------
// one thread per (b,d,s); 16-lane shfl reduce over s; lane s==0 writes gated y.
__global__ void scan_kernel(const float* __restrict__ dt, const float* __restrict__ dbl,
                            const float* __restrict__ xc, const float* __restrict__ xz,
                            const float* __restrict__ A_log, const float* __restrict__ Dp,
                            float* __restrict__ ys, int L)
{
    int idx = blockIdx.x * blockDim.x + threadIdx.x; // BATCH*DI*DS threads exact
    int s = idx & 15;
    int bd = idx >> 4;
    int d = bd % DI_;
    int b = bd / DI_;
    float Av = -__expf(A_log[d * DS_ + s]);
    float Dv = Dp[d];
    float h = 0.f;
    const float* dt_p = dt + (size_t)b * L * DI_ + d;
    const float* xc_p = xc + (size_t)b * L * DI_ + d;
    const float* z_p = xz + (size_t)b * L * (2 * DI_) + DI_ + d;
    const float* bl_p = dbl + (size_t)b * L * 80;
    float* ys_p = ys + (size_t)b * L * DI_ + d;
    for (int t = 0; t < L; t++) {
        float dtv = dt_p[(size_t)t * DI_];
        float xcv = xc_p[(size_t)t * DI_];
        float Bv = bl_p[(size_t)t * 80 + 48 + s];
        float Cv = bl_p[(size_t)t * 80 + 64 + s];
        h = __expf(dtv * Av) * h + dtv * Bv * xcv;
        float p = h * Cv;
        p += __shfl_xor_sync(0xffffffffu, p, 8);
        p += __shfl_xor_sync(0xffffffffu, p, 4);
        p += __shfl_xor_sync(0xffffffffu, p, 2);
        p += __shfl_xor_sync(0xffffffffu, p, 1);
        if (s == 0) {
            float y = p + Dv * xcv;
            float zv = z_p[(size_t)t * (2 * DI_)];
            ys_p[(size_t)t * DI_] = y * siluf(zv);
        }
    }
}

// ---------------- local cross-attention (each query attends <=3 keys) ----------------
__global__ void attn_kernel(const float* __restrict__ q, const float* __restrict__ k,
                            const float* __restrict__ v, float* __restrict__ o)
{
    int idx = blockIdx.x * blockDim.x + threadIdx.x;
    if (idx >= BATCH_ * NQ_ * NH_) return;
    int h = idx % NH_;
    int qi = (idx / NH_) % NQ_;
    int b = idx / (NH_ * NQ_);
    const int kpq = LSEQ_ / NQ_;   // 2
    const int extra = LSEQ_ % NQ_; // 256
    int start = qi * kpq + (qi < extra ? qi : extra);
    int cnt = kpq + (qi < extra ? 1 : 0);
    const float* qp = q + ((size_t)(b * NQ_ + qi)) * DIMM + h * HD_;
    float s[3];
    float mx = -1e30f;
    for (int j = 0; j < cnt; j++) {
        const float* kp = k + ((size_t)(b * LSEQ_ + start + j)) * DIMM + h * HD_;
        float dot = 0.f;
#pragma unroll
        for (int d = 0; d < HD_; d++) dot += qp[d] * kp[d];
        dot *= 0.14433756729740643f; // 1/sqrt(48)
        s[j] = dot;
        if (dot > mx) mx = dot;
    }
    float sum = 0.f;
    for (int j = 0; j < cnt; j++) { s[j] = expf(s[j] - mx); sum += s[j]; }
    float inv = 1.f / sum;
    float* op = o + ((size_t)(b * NQ_ + qi)) * DIMM + h * HD_;
    for (int d = 0; d < HD_; d++) {
        float acc = 0.f;
        for (int j = 0; j < cnt; j++)
            acc += s[j] * v[((size_t)(b * LSEQ_ + start + j)) * DIMM + h * HD_ + d];
        op[d] = acc * inv;
    }
}

// ---------------- elementwise utility kernels ----------------
__global__ void flip_kernel(const float* __restrict__ in, float* __restrict__ out, int L)
{
    int idx = blockIdx.x * blockDim.x + threadIdx.x;
    int total = BATCH_ * L * DIMM;
    if (idx >= total) return;
    int d = idx % DIMM;
    int l = (idx / DIMM) % L;
    int b = idx / (DIMM * L);
    out[idx] = in[((size_t)b * L + (L - 1 - l)) * DIMM + d];
}

// c = fwd + flip(mo) + feats
__global__ void add3_kernel(const float* __restrict__ fwd, const float* __restrict__ mo,
                            const float* __restrict__ feats, float* __restrict__ c, int L)
{
    int idx = blockIdx.x * blockDim.x + threadIdx.x;
    int total = BATCH_ * L * DIMM;
    if (idx >= total) return;
    int d = idx % DIMM;
    int l = (idx / DIMM) % L;
    int b = idx / (DIMM * L);
    c[idx] = fwd[idx] + mo[((size_t)b * L + (L - 1 - l)) * DIMM + d] + feats[idx];
}

__global__ void bcast_kernel(const float* __restrict__ queries, float* __restrict__ x)
{
    int idx = blockIdx.x * blockDim.x + threadIdx.x;
    int total = BATCH_ * NQ_ * DIMM;
    if (idx >= total) return;
    x[idx] = queries[idx % (NQ_ * DIMM)];
}

__global__ void concat_kernel(const float* __restrict__ a, const float* __restrict__ b,
                              float* __restrict__ c)
{
    int idx = blockIdx.x * blockDim.x + threadIdx.x;
    int total = BATCH_ * NQ_ * 2 * DIMM;
    if (idx >= total) return;
    int col = idx % (2 * DIMM);
    int r = idx / (2 * DIMM);
    c[idx] = (col < DIMM) ? a[(size_t)r * DIMM + col] : b[(size_t)r * DIMM + col - DIMM];
}

__global__ void copy_kernel(const float* __restrict__ a, float* __restrict__ b, int n)
{
    int idx = blockIdx.x * blockDim.x + threadIdx.x;
    if (idx < n) b[idx] = a[idx];
}

// ---------------- host orchestration ----------------
extern "C" void kernel_launch(void* const* d_in, const int* in_sizes, int n_in,
                              void* d_out, int out_size)
{
    (void)in_sizes; (void)n_in;
    const float* img_emb   = (const float*)d_in[0];
    const float* queries   = (const float*)d_in[1];
    const float* vproj_w   = (const float*)d_in[2];
    const float* vproj_b   = (const float*)d_in[3];
    const float* lnv_g     = (const float*)d_in[4];
    const float* lnv_b     = (const float*)d_in[5];
    const float* m_in_w    = (const float*)d_in[6];
    const float* m_conv_w  = (const float*)d_in[7];
    const float* m_conv_b  = (const float*)d_in[8];
    const float* m_xproj_w = (const float*)d_in[9];
    const float* m_dt_w    = (const float*)d_in[10];
    const float* m_dt_b    = (const float*)d_in[11];
    const float* m_A_log   = (const float*)d_in[12];
    const float* m_D       = (const float*)d_in[13];
    const float* m_out_w   = (const float*)d_in[14];
    const float* sn_g      = (const float*)d_in[15];
    const float* sn_b      = (const float*)d_in[16];
    const float* at_in_w   = (const float*)d_in[17];
    const float* at_in_b   = (const float*)d_in[18];
    const float* at_out_w  = (const float*)d_in[19];
    const float* at_out_b  = (const float*)d_in[20];
    const float* cr_w      = (const float*)d_in[21];
    const float* cr_b      = (const float*)d_in[22];

    float* AR = nullptr;
    cudaGetSymbolAddress((void**)&AR, g_arena);

    float* feats = AR + OFF_FEATS;
    float* fwd   = AR + OFF_FWD;
    float* flip  = AR + OFF_FLIP;
    float* cbuf  = AR + OFF_C;
    float* mo    = AR + OFF_MO;
    float* xzb   = AR + OFF_XZ;
    float* xcb   = AR + OFF_XCB;
    float* dblb  = AR + OFF_DBL;
    float* dtb   = AR + OFF_DT;
    float* ysb   = AR + OFF_YS;
    float* xb    = AR + OFF_X;
    float* xnb   = AR + OFF_XN;
    float* qb    = AR + OFF_QB;
    float* kb    = AR + OFF_KB;
    float* vb    = AR + OFF_VB;
    float* ob    = AR + OFF_OB;
    float* scoreb = AR + OFF_SCORE;
    float* catb  = AR + OFF_CAT;

    auto run_mamba = [&](const float* X, int Lm, int i, float* OUT, const float* addend) {
        int Mrows = BATCH_ * Lm;
        // xz = X @ in_w.T
        gemm(X, DIMM, m_in_w + (size_t)i * 2 * DI_ * DIMM, DIMM,
             nullptr, nullptr, 0, xzb, 2 * DI_, Mrows, 2 * DI_, DIMM, 0);
        // depthwise conv + silu -> xc
        conv_kernel<<<(BATCH_ * Lm * DI_ + 255) / 256, 256>>>(
            xzb, m_conv_w + (size_t)i * DI_ * DC_, m_conv_b + (size_t)i * DI_, xcb, Lm);
        // dbl = xc @ xproj.T
        gemm(xcb, DI_, m_xproj_w + (size_t)i * 80 * DI_, DI_,
             nullptr, nullptr, 0, dblb, 80, Mrows, 80, DI_, 0);
        // dt = softplus(dbl[:, :48] @ dt_w.T + dt_b)
        gemm(dblb, 80, m_dt_w + (size_t)i * DI_ * DTR_, DTR_,
             m_dt_b + (size_t)i * DI_, nullptr, 0, dtb, DI_, Mrows, DI_, DTR_, 1);
        // scan + gate -> ys
        scan_kernel<<<(BATCH_ * DI_ * DS_) / 256, 256>>>(
            dtb, dblb, xcb, xzb, m_A_log + (size_t)i * DI_ * DS_,
            m_D + (size_t)i * DI_, ysb, Lm);
        // OUT = ys @ out_w.T (+ addend)
        gemm(ysb, DI_, m_out_w + (size_t)i * DIMM * DI_, DI_,
             nullptr, addend, DIMM, OUT, DIMM, Mrows, DIMM, DI_, 0);
    };

    // ---- Stage A: feats = LN(img_emb @ vproj.T + b) ----
    gemm(img_emb, DIN_, vproj_w, DIN_, vproj_b, nullptr, 0,
         feats, DIMM, BATCH_ * LSEQ_, DIMM, DIN_, 0);
    ln_kernel<<<BATCH_ * LSEQ_, 256>>>(feats, lnv_g, lnv_b, feats); // in-place safe

    // ---- Stage B: bidirectional mamba -> c ----
    run_mamba(feats, LSEQ_, 0, fwd, nullptr);
    flip_kernel<<<(BATCH_ * LSEQ_ * DIMM + 255) / 256, 256>>>(feats, flip, LSEQ_);
    run_mamba(flip, LSEQ_, 1, mo, nullptr);
    add3_kernel<<<(BATCH_ * LSEQ_ * DIMM + 255) / 256, 256>>>(fwd, mo, feats, cbuf, LSEQ_);

    // ---- Stage C: query blocks ----
    bcast_kernel<<<(BATCH_ * NQ_ * DIMM + 255) / 256, 256>>>(queries, xb);

    for (int l = 0; l < NB_; l++) {
        // xn = LN(x)
        ln_kernel<<<BATCH_ * NQ_, 256>>>(xb, sn_g + (size_t)l * DIMM, sn_b + (size_t)l * DIMM, xnb);
        // x = mamba(xn) + xn
        run_mamba(xnb, NQ_, l + 2, xb, xnb);
        // q/k/v
        const float* wq = at_in_w + (size_t)l * 3 * DIMM * DIMM;
        const float* wk = wq + (size_t)DIMM * DIMM;
        const float* wv = wk + (size_t)DIMM * DIMM;
        const float* bq = at_in_b + (size_t)l * 3 * DIMM;
        const float* bk = bq + DIMM;
        const float* bv = bk + DIMM;
        gemm(xb, DIMM, wq, DIMM, bq, nullptr, 0, qb, DIMM, BATCH_ * NQ_, DIMM, DIMM, 0);
        gemm(cbuf, DIMM, wk, DIMM, bk, nullptr, 0, kb, DIMM, BATCH_ * LSEQ_, DIMM, DIMM, 0);
        gemm(cbuf, DIMM, wv, DIMM, bv, nullptr, 0, vb, DIMM, BATCH_ * LSEQ_, DIMM, DIMM, 0);
        // local attention
        attn_kernel<<<(BATCH_ * NQ_ * NH_ + 127) / 128, 128>>>(qb, kb, vb, ob);
        // score = o @ out_w.T + out_b
        gemm(ob, DIMM, at_out_w + (size_t)l * DIMM * DIMM, DIMM,
             at_out_b + (size_t)l * DIMM, nullptr, 0, scoreb, DIMM, BATCH_ * NQ_, DIMM, DIMM, 0);
        // x = [x, score] @ cross_w.T + cross_b
        concat_kernel<<<(BATCH_ * NQ_ * 2 * DIMM + 255) / 256, 256>>>(xb, scoreb, catb);
        gemm(catb, 2 * DIMM, cr_w + (size_t)l * DIMM * 2 * DIMM, 2 * DIMM,
             cr_b + (size_t)l * DIMM, nullptr, 0, xb, DIMM, BATCH_ * NQ_, DIMM, 2 * DIMM, 0);
    }

    copy_kernel<<<(out_size + 255) / 256, 256>>>(xb, (float*)d_out, out_size);
}

// round 2
// speedup vs baseline: 1.3699x; 1.3699x over previous
#include <cuda_runtime.h>
#include <math.h>
#include <stdint.h>

#define DIMM 768
#define DIN_ 1024
#define NQ_ 384
#define NB_ 12
#define BATCH_ 2
#define LSEQ_ 1024
#define DI_ 1536
#define DS_ 16
#define DC_ 4
#define DTR_ 48
#define NH_ 16
#define HD_ 48
#define NM_ 14

// ---------------- arena ----------------
#define SZ_BL_DIM   (BATCH_*LSEQ_*DIMM)
#define SZ_XZ       (BATCH_*LSEQ_*2*DI_)
#define SZ_XC       (BATCH_*LSEQ_*DI_)
#define SZ_DBL      (BATCH_*LSEQ_*80)
#define SZ_Q_DIM    (BATCH_*NQ_*DIMM)
#define SZ_CAT      (BATCH_*NQ_*2*DIMM)
#define SZ_KV       (BATCH_*LSEQ_*2*DIMM)
#define SZ_PART     (4*1024*1024)

#define OFF_FEATS  ((size_t)0)
#define OFF_FWD    (OFF_FEATS + SZ_BL_DIM)
#define OFF_FLIP   (OFF_FWD   + SZ_BL_DIM)
#define OFF_C      (OFF_FLIP  + SZ_BL_DIM)
#define OFF_MO     (OFF_C     + SZ_BL_DIM)
#define OFF_XZ     (OFF_MO    + SZ_BL_DIM)
#define OFF_XCB    (OFF_XZ    + SZ_XZ)
#define OFF_DBL    (OFF_XCB   + SZ_XC)
#define OFF_DT     (OFF_DBL   + SZ_DBL)
#define OFF_YS     (OFF_DT    + SZ_XC)
#define OFF_X      (OFF_YS    + SZ_XC)
#define OFF_XN     (OFF_X     + SZ_Q_DIM)
#define OFF_QB     (OFF_XN    + SZ_Q_DIM)
#define OFF_KV     (OFF_QB    + SZ_Q_DIM)
#define OFF_OB     (OFF_KV    + SZ_KV)
#define OFF_SCORE  (OFF_OB    + SZ_Q_DIM)
#define OFF_CAT    (OFF_SCORE + SZ_Q_DIM)
#define OFF_PART   (OFF_CAT   + SZ_CAT)
#define ARENA_SZ   (OFF_PART  + SZ_PART)

__device__ __align__(256) float g_arena[ARENA_SZ];

// ---------------- helpers ----------------
__device__ __forceinline__ float softplusf(float x) {
    return fmaxf(x, 0.f) + log1pf(expf(-fabsf(x)));
}
__device__ __forceinline__ float siluf(float x) {
    return x / (1.f + expf(-x));
}

// ============ big SGEMM: 128x128 tile, 8x8 micro, BK=8, double-buffered ============
// C = act(A @ B^T + bias) + addend   (epilogue only when launched as final pass)
// A: (M,K) lda; B: (N,K) ldb. blockIdx.z = K-split index; klen = K/split.
__global__ __launch_bounds__(256) void gemm128_kernel(
    const float* __restrict__ A, int lda,
    const float* __restrict__ B, int ldb,
    const float* __restrict__ bias,
    const float* __restrict__ addend, int ldadd,
    float* __restrict__ C, int ldc, size_t zstride,
    int M, int N, int klen, int act)
{
    __shared__ __align__(16) float As[2][8][128];
    __shared__ __align__(16) float Bs[2][8][128];
    int tid = threadIdx.x;
    int bm = blockIdx.y * 128, bn = blockIdx.x * 128;
    int kbeg = blockIdx.z * klen;

    int lrow = tid & 127;
    int lk = (tid >> 7) * 4;

    bool aval = (bm + lrow) < M;
    bool bval = (bn + lrow) < N;
    int arow = aval ? (bm + lrow) : (M - 1);
    int brow = bval ? (bn + lrow) : (N - 1);
    const float* Ap = A + (size_t)arow * lda + kbeg + lk;
    const float* Bp = B + (size_t)brow * ldb + kbeg + lk;

    const float4 z4 = make_float4(0.f, 0.f, 0.f, 0.f);
    float4 av = aval ? *(const float4*)Ap : z4;
    float4 bv = bval ? *(const float4*)Bp : z4;
    As[0][lk+0][lrow] = av.x; As[0][lk+1][lrow] = av.y;
    As[0][lk+2][lrow] = av.z; As[0][lk+3][lrow] = av.w;
    Bs[0][lk+0][lrow] = bv.x; Bs[0][lk+1][lrow] = bv.y;
    Bs[0][lk+2][lrow] = bv.z; Bs[0][lk+3][lrow] = bv.w;
    __syncthreads();

    int tx = tid & 15, ty = tid >> 4;
    float acc[8][8];
#pragma unroll
    for (int i = 0; i < 8; i++)
#pragma unroll
        for (int j = 0; j < 8; j++) acc[i][j] = 0.f;

    int p = 0;
    for (int k0 = 8; k0 <= klen; k0 += 8) {
        float4 av2 = z4, bv2 = z4;
        bool more = (k0 < klen);
        if (more) {
            if (aval) av2 = *(const float4*)(Ap + k0);
            if (bval) bv2 = *(const float4*)(Bp + k0);
        }
#pragma unroll
        for (int kk = 0; kk < 8; kk++) {
            float4 a0 = *(const float4*)&As[p][kk][ty * 8];
            float4 a1 = *(const float4*)&As[p][kk][ty * 8 + 4];
            float4 b0 = *(const float4*)&Bs[p][kk][tx * 8];
            float4 b1 = *(const float4*)&Bs[p][kk][tx * 8 + 4];
            float a[8] = {a0.x, a0.y, a0.z, a0.w, a1.x, a1.y, a1.z, a1.w};
            float b[8] = {b0.x, b0.y, b0.z, b0.w, b1.x, b1.y, b1.z, b1.w};
#pragma unroll
            for (int i = 0; i < 8; i++)
#pragma unroll
                for (int j = 0; j < 8; j++) acc[i][j] += a[i] * b[j];
        }
        if (more) {
            int q = p ^ 1;
            As[q][lk+0][lrow] = av2.x; As[q][lk+1][lrow] = av2.y;
            As[q][lk+2][lrow] = av2.z; As[q][lk+3][lrow] = av2.w;
            Bs[q][lk+0][lrow] = bv2.x; Bs[q][lk+1][lrow] = bv2.y;
            Bs[q][lk+2][lrow] = bv2.z; Bs[q][lk+3][lrow] = bv2.w;
            __syncthreads();
            p = q;
        }
    }

    float* Cz = C + (size_t)blockIdx.z * zstride;
#pragma unroll
    for (int i = 0; i < 8; i++) {
        int m = bm + ty * 8 + i;
        if (m >= M) continue;
#pragma unroll
        for (int j = 0; j < 8; j++) {
            int n = bn + tx * 8 + j;
            if (n >= N) continue;
            float v = acc[i][j];
            if (bias) v += bias[n];
            if (act == 1) v = softplusf(v);
            if (addend) v += addend[(size_t)m * ldadd + n];
            Cz[(size_t)m * ldc + n] = v;
        }
    }
}

// ============ small SGEMM: 64x64 tile, 4x4 micro (for N<128) ============
__global__ void gemm64_kernel(const float* __restrict__ A, int lda,
                              const float* __restrict__ B, int ldb,
                              const float* __restrict__ bias,
                              const float* __restrict__ addend, int ldadd,
                              float* __restrict__ C, int ldc, size_t zstride,
                              int M, int N, int klen, int act)
{
    __shared__ __align__(16) float As[16][64];
    __shared__ __align__(16) float Bs[16][64];
    int tid = threadIdx.x;
    int tx = tid & 15, ty = tid >> 4;
    int bm = blockIdx.y * 64, bn = blockIdx.x * 64;
    int kbeg = blockIdx.z * klen;

    float acc[4][4];
#pragma unroll
    for (int i = 0; i < 4; i++)
#pragma unroll
        for (int j = 0; j < 4; j++) acc[i][j] = 0.f;

    for (int k0 = 0; k0 < klen; k0 += 16) {
#pragma unroll
        for (int r = 0; r < 4; r++) {
            int i = tid + r * 256;
            int m = i >> 4, kk = i & 15;
            int gm = bm + m;
            As[kk][m] = (gm < M) ? A[(size_t)gm * lda + kbeg + k0 + kk] : 0.f;
        }
#pragma unroll
        for (int r = 0; r < 4; r++) {
            int i = tid + r * 256;
            int n = i >> 4, kk = i & 15;
            int gn = bn + n;
            Bs[kk][n] = (gn < N) ? B[(size_t)gn * ldb + kbeg + k0 + kk] : 0.f;
        }
        __syncthreads();
#pragma unroll
        for (int kk = 0; kk < 16; kk++) {
            float4 a4 = *reinterpret_cast<const float4*>(&As[kk][ty * 4]);
            float4 b4 = *reinterpret_cast<const float4*>(&Bs[kk][tx * 4]);
            float a[4] = {a4.x, a4.y, a4.z, a4.w};
            float bb[4] = {b4.x, b4.y, b4.z, b4.w};
#pragma unroll
            for (int i = 0; i < 4; i++)
#pragma unroll
                for (int j = 0; j < 4; j++) acc[i][j] += a[i] * bb[j];
        }
        __syncthreads();
    }

    float* Cz = C + (size_t)blockIdx.z * zstride;
#pragma unroll
    for (int i = 0; i < 4; i++) {
        int m = bm + ty * 4 + i;
        if (m >= M) continue;
#pragma unroll
        for (int j = 0; j < 4; j++) {
            int n = bn + tx * 4 + j;
            if (n >= N) continue;
            float v = acc[i][j];
            if (bias) v += bias[n];
            if (act == 1) v = softplusf(v);
            if (addend) v += addend[(size_t)m * ldadd + n];
            Cz[(size_t)m * ldc + n] = v;
        }
    }
}

// ============ split-K reduce with epilogue ============
__global__ void reduce_kernel(const float* __restrict__ part, size_t pstride, int nsplit,
                              const float* __restrict__ bias,
                              const float* __restrict__ addend, int ldadd,
                              float* __restrict__ C, int ldc, int M, int N, int act)
{
    int idx = blockIdx.x * blockDim.x + threadIdx.x;
    if (idx >= M * N) return;
    int m = idx / N, n = idx % N;
    float v = 0.f;
    for (int z = 0; z < nsplit; z++) v += part[(size_t)z * pstride + idx];
    if (bias) v += bias[n];
    if (act == 1) v = softplusf(v);
    if (addend) v += addend[(size_t)m * ldadd + n];
    C[(size_t)m * ldc + n] = v;
}

static float* g_partial = nullptr;

static void gemm(const float* A, int lda, const float* B, int ldb,
                 const float* bias, const float* addend, int ldadd,
                 float* C, int ldc, int M, int N, int K, int act)
{
    if (N >= 128) {
        int gm = (M + 127) / 128, gn = (N + 127) / 128;
        int split = 1;
        while (gm * gn * split < 120 && split < 8 &&
               (K % (split * 2 * 8)) == 0 && (K / (split * 2)) >= 96) split *= 2;
        int klen = K / split;
        dim3 grid(gn, gm, split);
        if (split == 1) {
            gemm128_kernel<<<grid, 256>>>(A, lda, B, ldb, bias, addend, ldadd,
                                          C, ldc, 0, M, N, klen, act);
        } else {
            gemm128_kernel<<<grid, 256>>>(A, lda, B, ldb, nullptr, nullptr, 0,
                                          g_partial, N, (size_t)M * N, M, N, klen, 0);
            reduce_kernel<<<(M * N + 255) / 256, 256>>>(g_partial, (size_t)M * N, split,
                                                        bias, addend, ldadd, C, ldc, M, N, act);
        }
    } else {
        int gm = (M + 63) / 64, gn = (N + 63) / 64;
        int split = 1;
        while (gm * gn * split < 120 && split < 8 &&
               (K % (split * 2 * 16)) == 0 && (K / (split * 2)) >= 96) split *= 2;
        int klen = K / split;
        dim3 grid(gn, gm, split);
        if (split == 1) {
            gemm64_kernel<<<grid, 256>>>(A, lda, B, ldb, bias, addend, ldadd,
                                         C, ldc, 0, M, N, klen, act);
        } else {
            gemm64_kernel<<<grid, 256>>>(A, lda, B, ldb, nullptr, nullptr, 0,
                                         g_partial, N, (size_t)M * N, M, N, klen, 0);
            reduce_kernel<<<(M * N + 255) / 256, 256>>>(g_partial, (size_t)M * N, split,
                                                        bias, addend, ldadd, C, ldc, M, N, act);
        }
    }
}

// ---------------- layernorm ----------------
__global__ void ln_kernel(const float* __restrict__ x, const float* __restrict__ g,
                          const float* __restrict__ b, float* __restrict__ y)
{
    int r = blockIdx.x;
    const float* xp = x + (size_t)r * DIMM;
    float s = 0.f, ss = 0.f;
    for (int i = threadIdx.x; i < DIMM; i += blockDim.x) {
        float v = xp[i]; s += v; ss += v * v;
    }
    __shared__ float shs[8], shss[8];
    for (int o = 16; o > 0; o >>= 1) {
        s += __shfl_xor_sync(0xffffffffu, s, o);
        ss += __shfl_xor_sync(0xffffffffu, ss, o);
    }
    int w = threadIdx.x >> 5;
    if ((threadIdx.x & 31) == 0) { shs[w] = s; shss[w] = ss; }
    __syncthreads();
    if (threadIdx.x == 0) {
        float ts = 0.f, tss = 0.f;
        int nw = blockDim.x >> 5;
        for (int i = 0; i < nw; i++) { ts += shs[i]; tss += shss[i]; }
        shs[0] = ts; shss[0] = tss;
    }
    __syncthreads();
    float mean = shs[0] / (float)DIMM;
    float var = shss[0] / (float)DIMM - mean * mean;
    float inv = rsqrtf(var + 1e-5f);
    float* yp = y + (size_t)r * DIMM;
    for (int i = threadIdx.x; i < DIMM; i += blockDim.x)
        yp[i] = (xp[i] - mean) * inv * g[i] + b[i];
}

// ---------------- depthwise causal conv + silu ----------------
__global__ void conv_kernel(const float* __restrict__ xz, const float* __restrict__ cw,
                            const float* __restrict__ cb, float* __restrict__ xc, int L)
{
    int idx = blockIdx.x * blockDim.x + threadIdx.x;
    int total = BATCH_ * L * DI_;
    if (idx >= total) return;
    int d = idx % DI_;
    int l = (idx / DI_) % L;
    int b = idx / (DI_ * L);
    float sum = cb[d];
    const float* base = xz + ((size_t)b * L) * (2 * DI_) + d;
#pragma unroll
    for (int j = 0; j < DC_; j++) {
        int lt = l - (DC_ - 1) + j;
        if (lt >= 0) sum += base[(size_t)lt * (2 * DI_)] * cw[d * DC_ + j];
    }
    xc[idx] = siluf(sum);
}

// ---------------- selective scan ----------------
__global__ void scan_kernel(const float* __restrict__ dt, const float* __restrict__ dbl,
                            const float* __restrict__ xc, const float* __restrict__ xz,
                            const float* __restrict__ A_log, const float* __restrict__ Dp,
                            float* __restrict__ ys, int L)
{
    int idx = blockIdx.x * blockDim.x + threadIdx.x;
    int s = idx & 15;
    int bd = idx >> 4;
    int d = bd % DI_;
    int b = bd / DI_;
    float Av = -__expf(A_log[d * DS_ + s]);
    float Dv = Dp[d];
    float h = 0.f;
    const float* dt_p = dt + (size_t)b * L * DI_ + d;
    const float* xc_p = xc + (size_t)b * L * DI_ + d;
    const float* z_p = xz + (size_t)b * L * (2 * DI_) + DI_ + d;
    const float* bl_p = dbl + (size_t)b * L * 80;
    float* ys_p = ys + (size_t)b * L * DI_ + d;
    for (int t = 0; t < L; t++) {
        float dtv = dt_p[(size_t)t * DI_];
        float xcv = xc_p[(size_t)t * DI_];
        float Bv = bl_p[(size_t)t * 80 + 48 + s];
        float Cv = bl_p[(size_t)t * 80 + 64 + s];
        h = __expf(dtv * Av) * h + dtv * Bv * xcv;
        float p = h * Cv;
        p += __shfl_xor_sync(0xffffffffu, p, 8);
        p += __shfl_xor_sync(0xffffffffu, p, 4);
        p += __shfl_xor_sync(0xffffffffu, p, 2);
        p += __shfl_xor_sync(0xffffffffu, p, 1);
        if (s == 0) {
            float y = p + Dv * xcv;
            float zv = z_p[(size_t)t * (2 * DI_)];
            ys_p[(size_t)t * DI_] = y * siluf(zv);
        }
    }
}

// ---------------- local cross-attention (kv fused buffer, ld=1536) ----------------
__global__ void attn_kernel(const float* __restrict__ q, const float* __restrict__ kv,
                            float* __restrict__ o)
{
    int idx = blockIdx.x * blockDim.x + threadIdx.x;
    if (idx >= BATCH_ * NQ_ * NH_) return;
    int h = idx % NH_;
    int qi = (idx / NH_) % NQ_;
    int b = idx / (NH_ * NQ_);
    const int kpq = LSEQ_ / NQ_;
    const int extra = LSEQ_ % NQ_;
    int start = qi * kpq + (qi < extra ? qi : extra);
    int cnt = kpq + (qi < extra ? 1 : 0);
    const float* qp = q + ((size_t)(b * NQ_ + qi)) * DIMM + h * HD_;
    float s[3];
    float mx = -1e30f;
    for (int j = 0; j < cnt; j++) {
        const float* kp = kv + ((size_t)(b * LSEQ_ + start + j)) * (2 * DIMM) + h * HD_;
        float dot = 0.f;
#pragma unroll
        for (int d = 0; d < HD_; d++) dot += qp[d] * kp[d];
        dot *= 0.14433756729740643f;
        s[j] = dot;
        if (dot > mx) mx = dot;
    }
    float sum = 0.f;
    for (int j = 0; j < cnt; j++) { s[j] = expf(s[j] - mx); sum += s[j]; }
    float inv = 1.f / sum;
    float* op = o + ((size_t)(b * NQ_ + qi)) * DIMM + h * HD_;
    for (int d = 0; d < HD_; d++) {
        float acc = 0.f;
        for (int j = 0; j < cnt; j++)
            acc += s[j] * kv[((size_t)(b * LSEQ_ + start + j)) * (2 * DIMM) + DIMM + h * HD_ + d];
        op[d] = acc * inv;
    }
}

// ---------------- elementwise utilities ----------------
__global__ void flip_kernel(const float* __restrict__ in, float* __restrict__ out, int L)
{
    int idx = blockIdx.x * blockDim.x + threadIdx.x;
    int total = BATCH_ * L * DIMM;
    if (idx >= total) return;
    int d = idx % DIMM;
    int l = (idx / DIMM) % L;
    int b = idx / (DIMM * L);
    out[idx] = in[((size_t)b * L + (L - 1 - l)) * DIMM + d];
}

__global__ void add3_kernel(const float* __restrict__ fwd, const float* __restrict__ mo,
                            const float* __restrict__ feats, float* __restrict__ c, int L)
{
    int idx = blockIdx.x * blockDim.x + threadIdx.x;
    int total = BATCH_ * L * DIMM;
    if (idx >= total) return;
    int d = idx % DIMM;
    int l = (idx / DIMM) % L;
    int b = idx / (DIMM * L);
    c[idx] = fwd[idx] + mo[((size_t)b * L + (L - 1 - l)) * DIMM + d] + feats[idx];
}

__global__ void bcast_kernel(const float* __restrict__ queries, float* __restrict__ x)
{
    int idx = blockIdx.x * blockDim.x + threadIdx.x;
    int total = BATCH_ * NQ_ * DIMM;
    if (idx >= total) return;
    x[idx] = queries[idx % (NQ_ * DIMM)];
}

__global__ void concat_kernel(const float* __restrict__ a, const float* __restrict__ b,
                              float* __restrict__ c)
{
    int idx = blockIdx.x * blockDim.x + threadIdx.x;
    int total = BATCH_ * NQ_ * 2 * DIMM;
    if (idx >= total) return;
    int col = idx % (2 * DIMM);
    int r = idx / (2 * DIMM);
    c[idx] = (col < DIMM) ? a[(size_t)r * DIMM + col] : b[(size_t)r * DIMM + col - DIMM];
}

__global__ void copy_kernel(const float* __restrict__ a, float* __restrict__ b, int n)
{
    int idx = blockIdx.x * blockDim.x + threadIdx.x;
    if (idx < n) b[idx] = a[idx];
}

// ---------------- host orchestration ----------------
extern "C" void kernel_launch(void* const* d_in, const int* in_sizes, int n_in,
                              void* d_out, int out_size)
{
    (void)in_sizes; (void)n_in;
    const float* img_emb   = (const float*)d_in[0];
    const float* queries   = (const float*)d_in[1];
    const float* vproj_w   = (const float*)d_in[2];
    const float* vproj_b   = (const float*)d_in[3];
    const float* lnv_g     = (const float*)d_in[4];
    const float* lnv_b     = (const float*)d_in[5];
    const float* m_in_w    = (const float*)d_in[6];
    const float* m_conv_w  = (const float*)d_in[7];
    const float* m_conv_b  = (const float*)d_in[8];
    const float* m_xproj_w = (const float*)d_in[9];
    const float* m_dt_w    = (const float*)d_in[10];
    const float* m_dt_b    = (const float*)d_in[11];
    const float* m_A_log   = (const float*)d_in[12];
    const float* m_D       = (const float*)d_in[13];
    const float* m_out_w   = (const float*)d_in[14];
    const float* sn_g      = (const float*)d_in[15];
    const float* sn_b      = (const float*)d_in[16];
    const float* at_in_w   = (const float*)d_in[17];
    const float* at_in_b   = (const float*)d_in[18];
    const float* at_out_w  = (const float*)d_in[19];
    const float* at_out_b  = (const float*)d_in[20];
    const float* cr_w      = (const float*)d_in[21];
    const float* cr_b      = (const float*)d_in[22];

    float* AR = nullptr;
    cudaGetSymbolAddress((void**)&AR, g_arena);
    g_partial = AR + OFF_PART;

    float* feats = AR + OFF_FEATS;
    float* fwd   = AR + OFF_FWD;
    float* flip  = AR + OFF_FLIP;
    float* cbuf  = AR + OFF_C;
    float* mo    = AR + OFF_MO;
    float* xzb   = AR + OFF_XZ;
    float* xcb   = AR + OFF_XCB;
    float* dblb  = AR + OFF_DBL;
    float* dtb   = AR + OFF_DT;
    float* ysb   = AR + OFF_YS;
    float* xb    = AR + OFF_X;
    float* xnb   = AR + OFF_XN;
    float* qb    = AR + OFF_QB;
    float* kvb   = AR + OFF_KV;
    float* ob    = AR + OFF_OB;
    float* scoreb = AR + OFF_SCORE;
    float* catb  = AR + OFF_CAT;

    auto run_mamba = [&](const float* X, int Lm, int i, float* OUT, const float* addend) {
        int Mrows = BATCH_ * Lm;
        gemm(X, DIMM, m_in_w + (size_t)i * 2 * DI_ * DIMM, DIMM,
             nullptr, nullptr, 0, xzb, 2 * DI_, Mrows, 2 * DI_, DIMM, 0);
        conv_kernel<<<(BATCH_ * Lm * DI_ + 255) / 256, 256>>>(
            xzb, m_conv_w + (size_t)i * DI_ * DC_, m_conv_b + (size_t)i * DI_, xcb, Lm);
        gemm(xcb, DI_, m_xproj_w + (size_t)i * 80 * DI_, DI_,
             nullptr, nullptr, 0, dblb, 80, Mrows, 80, DI_, 0);
        gemm(dblb, 80, m_dt_w + (size_t)i * DI_ * DTR_, DTR_,
             m_dt_b + (size_t)i * DI_, nullptr, 0, dtb, DI_, Mrows, DI_, DTR_, 1);
        scan_kernel<<<(BATCH_ * DI_ * DS_) / 256, 256>>>(
            dtb, dblb, xcb, xzb, m_A_log + (size_t)i * DI_ * DS_,
            m_D + (size_t)i * DI_, ysb, Lm);
        gemm(ysb, DI_, m_out_w + (size_t)i * DIMM * DI_, DI_,
             nullptr, addend, DIMM, OUT, DIMM, Mrows, DIMM, DI_, 0);
    };

    // ---- Stage A ----
    gemm(img_emb, DIN_, vproj_w, DIN_, vproj_b, nullptr, 0,
         feats, DIMM, BATCH_ * LSEQ_, DIMM, DIN_, 0);
    ln_kernel<<<BATCH_ * LSEQ_, 256>>>(feats, lnv_g, lnv_b, feats);

    // ---- Stage B ----
    run_mamba(feats, LSEQ_, 0, fwd, nullptr);
    flip_kernel<<<(BATCH_ * LSEQ_ * DIMM + 255) / 256, 256>>>(feats, flip, LSEQ_);
    run_mamba(flip, LSEQ_, 1, mo, nullptr);
    add3_kernel<<<(BATCH_ * LSEQ_ * DIMM + 255) / 256, 256>>>(fwd, mo, feats, cbuf, LSEQ_);

    // ---- Stage C ----
    bcast_kernel<<<(BATCH_ * NQ_ * DIMM + 255) / 256, 256>>>(queries, xb);

    for (int l = 0; l < NB_; l++) {
        ln_kernel<<<BATCH_ * NQ_, 256>>>(xb, sn_g + (size_t)l * DIMM, sn_b + (size_t)l * DIMM, xnb);
        run_mamba(xnb, NQ_, l + 2, xb, xnb);

        const float* wq = at_in_w + (size_t)l * 3 * DIMM * DIMM;
        const float* wkv = wq + (size_t)DIMM * DIMM;          // wk‖wv contiguous
        const float* bq = at_in_b + (size_t)l * 3 * DIMM;
        const float* bkv = bq + DIMM;

        gemm(xb, DIMM, wq, DIMM, bq, nullptr, 0, qb, DIMM, BATCH_ * NQ_, DIMM, DIMM, 0);
        gemm(cbuf, DIMM, wkv, DIMM, bkv, nullptr, 0, kvb, 2 * DIMM,
             BATCH_ * LSEQ_, 2 * DIMM, DIMM, 0);

        attn_kernel<<<(BATCH_ * NQ_ * NH_ + 127) / 128, 128>>>(qb, kvb, ob);

        gemm(ob, DIMM, at_out_w + (size_t)l * DIMM * DIMM, DIMM,
             at_out_b + (size_t)l * DIMM, nullptr, 0, scoreb, DIMM, BATCH_ * NQ_, DIMM, DIMM, 0);
        concat_kernel<<<(BATCH_ * NQ_ * 2 * DIMM + 255) / 256, 256>>>(xb, scoreb, catb);
        gemm(catb, 2 * DIMM, cr_w + (size_t)l * DIMM * 2 * DIMM, 2 * DIMM,
             cr_b + (size_t)l * DIMM, nullptr, 0, xb, DIMM, BATCH_ * NQ_, DIMM, 2 * DIMM, 0);
    }

    copy_kernel<<<(out_size + 255) / 256, 256>>>(xb, (float*)d_out, out_size);
}

// round 3
// speedup vs baseline: 1.9389x; 1.4154x over previous
#include <cuda_runtime.h>
#include <math.h>
#include <stdint.h>

#define DIMM 768
#define DIN_ 1024
#define NQ_ 384
#define NB_ 12
#define BATCH_ 2
#define LSEQ_ 1024
#define DI_ 1536
#define DS_ 16
#define DC_ 4
#define DTR_ 48
#define NH_ 16
#define HD_ 48
#define NM_ 14

// ---------------- arena ----------------
#define SZ_BL_DIM   (BATCH_*LSEQ_*DIMM)
#define SZ_XZ       (BATCH_*LSEQ_*2*DI_)
#define SZ_XC       (BATCH_*LSEQ_*DI_)
#define SZ_DBL      (BATCH_*LSEQ_*80)
#define SZ_Q_DIM    (BATCH_*NQ_*DIMM)
#define SZ_CAT      (BATCH_*NQ_*2*DIMM)
#define SZ_KV       (BATCH_*LSEQ_*2*DIMM)
#define SZ_PART     (8*1024*1024)

#define OFF_FEATS  ((size_t)0)
#define OFF_FWD    (OFF_FEATS + SZ_BL_DIM)
#define OFF_FLIP   (OFF_FWD   + SZ_BL_DIM)
#define OFF_C      (OFF_FLIP  + SZ_BL_DIM)
#define OFF_MO     (OFF_C     + SZ_BL_DIM)
#define OFF_XZ     (OFF_MO    + SZ_BL_DIM)
#define OFF_XCB    (OFF_XZ    + SZ_XZ)
#define OFF_DBL    (OFF_XCB   + SZ_XC)
#define OFF_DT     (OFF_DBL   + SZ_DBL)
#define OFF_YS     (OFF_DT    + SZ_XC)
#define OFF_X      (OFF_YS    + SZ_XC)
#define OFF_XN     (OFF_X     + SZ_Q_DIM)
#define OFF_QB     (OFF_XN    + SZ_Q_DIM)
#define OFF_KV     (OFF_QB    + SZ_Q_DIM)
#define OFF_OB     (OFF_KV    + SZ_KV)
#define OFF_SCORE  (OFF_OB    + SZ_Q_DIM)
#define OFF_CAT    (OFF_SCORE + SZ_Q_DIM)
#define OFF_PART   (OFF_CAT   + SZ_CAT)
#define ARENA_SZ   (OFF_PART  + SZ_PART)

__device__ __align__(256) float g_arena[ARENA_SZ];

// ---------------- helpers ----------------
__device__ __forceinline__ float softplusf(float x) {
    return fmaxf(x, 0.f) + log1pf(expf(-fabsf(x)));
}
__device__ __forceinline__ float siluf(float x) {
    return x / (1.f + expf(-x));
}
__device__ __forceinline__ uint32_t f2tf32(float x) {
    uint32_t r;
    asm("cvt.rna.tf32.f32 %0, %1;" : "=r"(r) : "f"(x));
    return r;
}

// ================= TF32 tensor-core GEMM =================
// C = act(A @ B^T + bias) + addend (epilogue applied only when split==1 path)
// 128x128 tile, BK=32, 256 thr, warp grid 4(M)x2(N), warp tile 32x64.
// smem rows padded to 36 floats (conflict-free for STS.128 and frag LDS).
#define TLDS 36
#define TSTAGE (128 * TLDS)

__global__ __launch_bounds__(256) void gemm_tf32_kernel(
    const float* __restrict__ A, int lda,
    const float* __restrict__ B, int ldb,
    const float* __restrict__ bias,
    const float* __restrict__ addend, int ldadd,
    float* __restrict__ C, int ldc, size_t zstride,
    int M, int N, int klen, int act)
{
    extern __shared__ uint32_t sm_[];
    uint32_t* As = sm_;                 // [2][128*36]
    uint32_t* Bs = sm_ + 2 * TSTAGE;    // [2][128*36]

    int tid = threadIdx.x;
    int bm = blockIdx.y * 128, bn = blockIdx.x * 128;
    int kbeg = blockIdx.z * klen, kend = kbeg + klen;

    int lrow = tid & 127;
    int koff = (tid >> 7) * 4;          // 0 or 4
    int arow = bm + lrow, brow = bn + lrow;
    bool avalid = arow < M, bvalid = brow < N;
    const float* Ap = A + (size_t)(avalid ? arow : 0) * lda;
    const float* Bp = B + (size_t)(bvalid ? brow : 0) * ldb;

    // ---- load one stage (kbase..kbase+31) into buffer s ----
    auto load_stage = [&](int s, int kbase) {
        uint32_t* as = As + s * TSTAGE;
        uint32_t* bs = Bs + s * TSTAGE;
#pragma unroll
        for (int q = 0; q < 4; q++) {
            int k = kbase + q * 8 + koff;
            bool kin = (k < kend);
            float4 av = (avalid && kin) ? *(const float4*)(Ap + k)
                                        : make_float4(0.f, 0.f, 0.f, 0.f);
            float4 bv = (bvalid && kin) ? *(const float4*)(Bp + k)
                                        : make_float4(0.f, 0.f, 0.f, 0.f);
            int kc = q * 8 + koff;
            uint32_t* ad = as + lrow * TLDS + kc;
            ad[0] = f2tf32(av.x); ad[1] = f2tf32(av.y);
            ad[2] = f2tf32(av.z); ad[3] = f2tf32(av.w);
            uint32_t* bd = bs + lrow * TLDS + kc;
            bd[0] = f2tf32(bv.x); bd[1] = f2tf32(bv.y);
            bd[2] = f2tf32(bv.z); bd[3] = f2tf32(bv.w);
        }
    };

    load_stage(0, kbeg);
    __syncthreads();

    int lane = tid & 31, warp = tid >> 5;
    int wm = warp & 3, wn = warp >> 2;
    int m0 = wm * 32, n0 = wn * 64;
    int lr = lane >> 2, lc = lane & 3;

    float acc[2][8][4];
#pragma unroll
    for (int mi = 0; mi < 2; mi++)
#pragma unroll
        for (int ni = 0; ni < 8; ni++)
#pragma unroll
            for (int r = 0; r < 4; r++) acc[mi][ni][r] = 0.f;

    int p = 0;
    int nsteps = (klen + 31) / 32;
    for (int step = 0; step < nsteps; step++) {
        if (step + 1 < nsteps) {
            load_stage(p ^ 1, kbeg + (step + 1) * 32);
        }
        const uint32_t* as = As + p * TSTAGE;
        const uint32_t* bs = Bs + p * TSTAGE;
#pragma unroll
        for (int kk = 0; kk < 32; kk += 8) {
            uint32_t af[2][4];
#pragma unroll
            for (int mi = 0; mi < 2; mi++) {
                int r0 = m0 + mi * 16 + lr;
                af[mi][0] = as[r0 * TLDS + kk + lc];
                af[mi][1] = as[(r0 + 8) * TLDS + kk + lc];
                af[mi][2] = as[r0 * TLDS + kk + lc + 4];
                af[mi][3] = as[(r0 + 8) * TLDS + kk + lc + 4];
            }
            uint32_t bf[8][2];
#pragma unroll
            for (int ni = 0; ni < 8; ni++) {
                int n = n0 + ni * 8 + lr;
                bf[ni][0] = bs[n * TLDS + kk + lc];
                bf[ni][1] = bs[n * TLDS + kk + lc + 4];
            }
#pragma unroll
            for (int mi = 0; mi < 2; mi++)
#pragma unroll
                for (int ni = 0; ni < 8; ni++) {
                    asm volatile(
                        "mma.sync.aligned.m16n8k8.row.col.f32.tf32.tf32.f32 "
                        "{%0,%1,%2,%3}, {%4,%5,%6,%7}, {%8,%9}, {%0,%1,%2,%3};"
                        : "+f"(acc[mi][ni][0]), "+f"(acc[mi][ni][1]),
                          "+f"(acc[mi][ni][2]), "+f"(acc[mi][ni][3])
                        : "r"(af[mi][0]), "r"(af[mi][1]), "r"(af[mi][2]), "r"(af[mi][3]),
                          "r"(bf[ni][0]), "r"(bf[ni][1]));
                }
        }
        __syncthreads();
        p ^= 1;
    }

    // ---- epilogue ----
    float* Cz = C + (size_t)blockIdx.z * zstride;
#pragma unroll
    for (int mi = 0; mi < 2; mi++) {
#pragma unroll
        for (int rh = 0; rh < 2; rh++) {
            int m = bm + m0 + mi * 16 + lr + rh * 8;
            if (m >= M) continue;
#pragma unroll
            for (int ni = 0; ni < 8; ni++) {
#pragma unroll
                for (int cc = 0; cc < 2; cc++) {
                    int n = bn + n0 + ni * 8 + 2 * lc + cc;
                    if (n >= N) continue;
                    float v = acc[mi][ni][rh * 2 + cc];
                    if (bias) v += bias[n];
                    if (act == 1) v = softplusf(v);
                    if (addend) v += addend[(size_t)m * ldadd + n];
                    Cz[(size_t)m * ldc + n] = v;
                }
            }
        }
    }
}

// ============ small fp32 SGEMM: 64x64 tile (for N<128) ============
__global__ void gemm64_kernel(const float* __restrict__ A, int lda,
                              const float* __restrict__ B, int ldb,
                              const float* __restrict__ bias,
                              const float* __restrict__ addend, int ldadd,
                              float* __restrict__ C, int ldc, size_t zstride,
                              int M, int N, int klen, int act)
{
    __shared__ __align__(16) float As[16][64];
    __shared__ __align__(16) float Bs[16][64];
    int tid = threadIdx.x;
    int tx = tid & 15, ty = tid >> 4;
    int bm = blockIdx.y * 64, bn = blockIdx.x * 64;
    int kbeg = blockIdx.z * klen;

    float acc[4][4];
#pragma unroll
    for (int i = 0; i < 4; i++)
#pragma unroll
        for (int j = 0; j < 4; j++) acc[i][j] = 0.f;

    for (int k0 = 0; k0 < klen; k0 += 16) {
#pragma unroll
        for (int r = 0; r < 4; r++) {
            int i = tid + r * 256;
            int m = i >> 4, kk = i & 15;
            int gm = bm + m;
            As[kk][m] = (gm < M) ? A[(size_t)gm * lda + kbeg + k0 + kk] : 0.f;
        }
#pragma unroll
        for (int r = 0; r < 4; r++) {
            int i = tid + r * 256;
            int n = i >> 4, kk = i & 15;
            int gn = bn + n;
            Bs[kk][n] = (gn < N) ? B[(size_t)gn * ldb + kbeg + k0 + kk] : 0.f;
        }
        __syncthreads();
#pragma unroll
        for (int kk = 0; kk < 16; kk++) {
            float4 a4 = *reinterpret_cast<const float4*>(&As[kk][ty * 4]);
            float4 b4 = *reinterpret_cast<const float4*>(&Bs[kk][tx * 4]);
            float a[4] = {a4.x, a4.y, a4.z, a4.w};
            float bb[4] = {b4.x, b4.y, b4.z, b4.w};
#pragma unroll
            for (int i = 0; i < 4; i++)
#pragma unroll
                for (int j = 0; j < 4; j++) acc[i][j] += a[i] * bb[j];
        }
        __syncthreads();
    }

    float* Cz = C + (size_t)blockIdx.z * zstride;
#pragma unroll
    for (int i = 0; i < 4; i++) {
        int m = bm + ty * 4 + i;
        if (m >= M) continue;
#pragma unroll
        for (int j = 0; j < 4; j++) {
            int n = bn + tx * 4 + j;
            if (n >= N) continue;
            float v = acc[i][j];
            if (bias) v += bias[n];
            if (act == 1) v = softplusf(v);
            if (addend) v += addend[(size_t)m * ldadd + n];
            Cz[(size_t)m * ldc + n] = v;
        }
    }
}

// ============ split-K reduce with epilogue ============
__global__ void reduce_kernel(const float* __restrict__ part, size_t pstride, int nsplit,
                              const float* __restrict__ bias,
                              const float* __restrict__ addend, int ldadd,
                              float* __restrict__ C, int ldc, int M, int N, int act)
{
    int idx = blockIdx.x * blockDim.x + threadIdx.x;
    if (idx >= M * N) return;
    int m = idx / N, n = idx % N;
    float v = 0.f;
    for (int z = 0; z < nsplit; z++) v += part[(size_t)z * pstride + idx];
    if (bias) v += bias[n];
    if (act == 1) v = softplusf(v);
    if (addend) v += addend[(size_t)m * ldadd + n];
    C[(size_t)m * ldc + n] = v;
}

static float* g_partial = nullptr;

#define TF32_SMEM (4 * TSTAGE * 4)

static void gemm(const float* A, int lda, const float* B, int ldb,
                 const float* bias, const float* addend, int ldadd,
                 float* C, int ldc, int M, int N, int K, int act)
{
    if (N >= 128) {
        int gm = (M + 127) / 128, gn = (N + 127) / 128;
        int split = 1;
        while (gm * gn * split < 120 && split < 8 &&
               (K % (split * 2)) == 0 && (K / (split * 2)) >= 64) split *= 2;
        int klen = K / split;
        dim3 grid(gn, gm, split);
        if (split == 1) {
            gemm_tf32_kernel<<<grid, 256, TF32_SMEM>>>(
                A, lda, B, ldb, bias, addend, ldadd, C, ldc, 0, M, N, klen, act);
        } else {
            gemm_tf32_kernel<<<grid, 256, TF32_SMEM>>>(
                A, lda, B, ldb, nullptr, nullptr, 0,
                g_partial, N, (size_t)M * N, M, N, klen, 0);
            reduce_kernel<<<(M * N + 255) / 256, 256>>>(g_partial, (size_t)M * N, split,
                                                        bias, addend, ldadd, C, ldc, M, N, act);
        }
    } else {
        int gm = (M + 63) / 64, gn = (N + 63) / 64;
        int split = 1;
        while (gm * gn * split < 120 && split < 8 &&
               (K % (split * 2 * 16)) == 0 && (K / (split * 2)) >= 96) split *= 2;
        int klen = K / split;
        dim3 grid(gn, gm, split);
        if (split == 1) {
            gemm64_kernel<<<grid, 256>>>(A, lda, B, ldb, bias, addend, ldadd,
                                         C, ldc, 0, M, N, klen, act);
        } else {
            gemm64_kernel<<<grid, 256>>>(A, lda, B, ldb, nullptr, nullptr, 0,
                                         g_partial, N, (size_t)M * N, M, N, klen, 0);
            reduce_kernel<<<(M * N + 255) / 256, 256>>>(g_partial, (size_t)M * N, split,
                                                        bias, addend, ldadd, C, ldc, M, N, act);
        }
    }
}

// ---------------- layernorm ----------------
__global__ void ln_kernel(const float* __restrict__ x, const float* __restrict__ g,
                          const float* __restrict__ b, float* __restrict__ y)
{
    int r = blockIdx.x;
    const float* xp = x + (size_t)r * DIMM;
    float s = 0.f, ss = 0.f;
    for (int i = threadIdx.x; i < DIMM; i += blockDim.x) {
        float v = xp[i]; s += v; ss += v * v;
    }
    __shared__ float shs[8], shss[8];
    for (int o = 16; o > 0; o >>= 1) {
        s += __shfl_xor_sync(0xffffffffu, s, o);
        ss += __shfl_xor_sync(0xffffffffu, ss, o);
    }
    int w = threadIdx.x >> 5;
    if ((threadIdx.x & 31) == 0) { shs[w] = s; shss[w] = ss; }
    __syncthreads();
    if (threadIdx.x == 0) {
        float ts = 0.f, tss = 0.f;
        int nw = blockDim.x >> 5;
        for (int i = 0; i < nw; i++) { ts += shs[i]; tss += shss[i]; }
        shs[0] = ts; shss[0] = tss;
    }
    __syncthreads();
    float mean = shs[0] / (float)DIMM;
    float var = shss[0] / (float)DIMM - mean * mean;
    float inv = rsqrtf(var + 1e-5f);
    float* yp = y + (size_t)r * DIMM;
    for (int i = threadIdx.x; i < DIMM; i += blockDim.x)
        yp[i] = (xp[i] - mean) * inv * g[i] + b[i];
}

// ---------------- depthwise causal conv + silu ----------------
__global__ void conv_kernel(const float* __restrict__ xz, const float* __restrict__ cw,
                            const float* __restrict__ cb, float* __restrict__ xc, int L)
{
    int idx = blockIdx.x * blockDim.x + threadIdx.x;
    int total = BATCH_ * L * DI_;
    if (idx >= total) return;
    int d = idx % DI_;
    int l = (idx / DI_) % L;
    int b = idx / (DI_ * L);
    float sum = cb[d];
    const float* base = xz + ((size_t)b * L) * (2 * DI_) + d;
#pragma unroll
    for (int j = 0; j < DC_; j++) {
        int lt = l - (DC_ - 1) + j;
        if (lt >= 0) sum += base[(size_t)lt * (2 * DI_)] * cw[d * DC_ + j];
    }
    xc[idx] = siluf(sum);
}

// ---------------- selective scan ----------------
__global__ void scan_kernel(const float* __restrict__ dt, const float* __restrict__ dbl,
                            const float* __restrict__ xc, const float* __restrict__ xz,
                            const float* __restrict__ A_log, const float* __restrict__ Dp,
                            float* __restrict__ ys, int L)
{
    int idx = blockIdx.x * blockDim.x + threadIdx.x;
    int s = idx & 15;
    int bd = idx >> 4;
    int d = bd % DI_;
    int b = bd / DI_;
    float Av = -__expf(A_log[d * DS_ + s]);
    float Dv = Dp[d];
    float h = 0.f;
    const float* dt_p = dt + (size_t)b * L * DI_ + d;
    const float* xc_p = xc + (size_t)b * L * DI_ + d;
    const float* z_p = xz + (size_t)b * L * (2 * DI_) + DI_ + d;
    const float* bl_p = dbl + (size_t)b * L * 80;
    float* ys_p = ys + (size_t)b * L * DI_ + d;
    for (int t = 0; t < L; t++) {
        float dtv = dt_p[(size_t)t * DI_];
        float xcv = xc_p[(size_t)t * DI_];
        float Bv = bl_p[(size_t)t * 80 + 48 + s];
        float Cv = bl_p[(size_t)t * 80 + 64 + s];
        h = __expf(dtv * Av) * h + dtv * Bv * xcv;
        float p = h * Cv;
        p += __shfl_xor_sync(0xffffffffu, p, 8);
        p += __shfl_xor_sync(0xffffffffu, p, 4);
        p += __shfl_xor_sync(0xffffffffu, p, 2);
        p += __shfl_xor_sync(0xffffffffu, p, 1);
        if (s == 0) {
            float y = p + Dv * xcv;
            float zv = z_p[(size_t)t * (2 * DI_)];
            ys_p[(size_t)t * DI_] = y * siluf(zv);
        }
    }
}

// ---------------- local cross-attention ----------------
__global__ void attn_kernel(const float* __restrict__ q, const float* __restrict__ kv,
                            float* __restrict__ o)
{
    int idx = blockIdx.x * blockDim.x + threadIdx.x;
    if (idx >= BATCH_ * NQ_ * NH_) return;
    int h = idx % NH_;
    int qi = (idx / NH_) % NQ_;
    int b = idx / (NH_ * NQ_);
    const int kpq = LSEQ_ / NQ_;
    const int extra = LSEQ_ % NQ_;
    int start = qi * kpq + (qi < extra ? qi : extra);
    int cnt = kpq + (qi < extra ? 1 : 0);
    const float* qp = q + ((size_t)(b * NQ_ + qi)) * DIMM + h * HD_;
    float s[3];
    float mx = -1e30f;
    for (int j = 0; j < cnt; j++) {
        const float* kp = kv + ((size_t)(b * LSEQ_ + start + j)) * (2 * DIMM) + h * HD_;
        float dot = 0.f;
#pragma unroll
        for (int d = 0; d < HD_; d++) dot += qp[d] * kp[d];
        dot *= 0.14433756729740643f;
        s[j] = dot;
        if (dot > mx) mx = dot;
    }
    float sum = 0.f;
    for (int j = 0; j < cnt; j++) { s[j] = expf(s[j] - mx); sum += s[j]; }
    float inv = 1.f / sum;
    float* op = o + ((size_t)(b * NQ_ + qi)) * DIMM + h * HD_;
    for (int d = 0; d < HD_; d++) {
        float acc = 0.f;
        for (int j = 0; j < cnt; j++)
            acc += s[j] * kv[((size_t)(b * LSEQ_ + start + j)) * (2 * DIMM) + DIMM + h * HD_ + d];
        op[d] = acc * inv;
    }
}

// ---------------- elementwise utilities ----------------
__global__ void flip_kernel(const float* __restrict__ in, float* __restrict__ out, int L)
{
    int idx = blockIdx.x * blockDim.x + threadIdx.x;
    int total = BATCH_ * L * DIMM;
    if (idx >= total) return;
    int d = idx % DIMM;
    int l = (idx / DIMM) % L;
    int b = idx / (DIMM * L);
    out[idx] = in[((size_t)b * L + (L - 1 - l)) * DIMM + d];
}

__global__ void add3_kernel(const float* __restrict__ fwd, const float* __restrict__ mo,
                            const float* __restrict__ feats, float* __restrict__ c, int L)
{
    int idx = blockIdx.x * blockDim.x + threadIdx.x;
    int total = BATCH_ * L * DIMM;
    if (idx >= total) return;
    int d = idx % DIMM;
    int l = (idx / DIMM) % L;
    int b = idx / (DIMM * L);
    c[idx] = fwd[idx] + mo[((size_t)b * L + (L - 1 - l)) * DIMM + d] + feats[idx];
}

__global__ void bcast_kernel(const float* __restrict__ queries, float* __restrict__ x)
{
    int idx = blockIdx.x * blockDim.x + threadIdx.x;
    int total = BATCH_ * NQ_ * DIMM;
    if (idx >= total) return;
    x[idx] = queries[idx % (NQ_ * DIMM)];
}

__global__ void concat_kernel(const float* __restrict__ a, const float* __restrict__ b,
                              float* __restrict__ c)
{
    int idx = blockIdx.x * blockDim.x + threadIdx.x;
    int total = BATCH_ * NQ_ * 2 * DIMM;
    if (idx >= total) return;
    int col = idx % (2 * DIMM);
    int r = idx / (2 * DIMM);
    c[idx] = (col < DIMM) ? a[(size_t)r * DIMM + col] : b[(size_t)r * DIMM + col - DIMM];
}

__global__ void copy_kernel(const float* __restrict__ a, float* __restrict__ b, int n)
{
    int idx = blockIdx.x * blockDim.x + threadIdx.x;
    if (idx < n) b[idx] = a[idx];
}

// ---------------- host orchestration ----------------
extern "C" void kernel_launch(void* const* d_in, const int* in_sizes, int n_in,
                              void* d_out, int out_size)
{
    (void)in_sizes; (void)n_in;
    const float* img_emb   = (const float*)d_in[0];
    const float* queries   = (const float*)d_in[1];
    const float* vproj_w   = (const float*)d_in[2];
    const float* vproj_b   = (const float*)d_in[3];
    const float* lnv_g     = (const float*)d_in[4];
    const float* lnv_b     = (const float*)d_in[5];
    const float* m_in_w    = (const float*)d_in[6];
    const float* m_conv_w  = (const float*)d_in[7];
    const float* m_conv_b  = (const float*)d_in[8];
    const float* m_xproj_w = (const float*)d_in[9];
    const float* m_dt_w    = (const float*)d_in[10];
    const float* m_dt_b    = (const float*)d_in[11];
    const float* m_A_log   = (const float*)d_in[12];
    const float* m_D       = (const float*)d_in[13];
    const float* m_out_w   = (const float*)d_in[14];
    const float* sn_g      = (const float*)d_in[15];
    const float* sn_b      = (const float*)d_in[16];
    const float* at_in_w   = (const float*)d_in[17];
    const float* at_in_b   = (const float*)d_in[18];
    const float* at_out_w  = (const float*)d_in[19];
    const float* at_out_b  = (const float*)d_in[20];
    const float* cr_w      = (const float*)d_in[21];
    const float* cr_b      = (const float*)d_in[22];

    static int smem_set = 0;
    if (!smem_set) {
        cudaFuncSetAttribute(gemm_tf32_kernel,
                             cudaFuncAttributeMaxDynamicSharedMemorySize, TF32_SMEM);
        smem_set = 1;
    }

    float* AR = nullptr;
    cudaGetSymbolAddress((void**)&AR, g_arena);
    g_partial = AR + OFF_PART;

    float* feats = AR + OFF_FEATS;
    float* fwd   = AR + OFF_FWD;
    float* flip  = AR + OFF_FLIP;
    float* cbuf  = AR + OFF_C;
    float* mo    = AR + OFF_MO;
    float* xzb   = AR + OFF_XZ;
    float* xcb   = AR + OFF_XCB;
    float* dblb  = AR + OFF_DBL;
    float* dtb   = AR + OFF_DT;
    float* ysb   = AR + OFF_YS;
    float* xb    = AR + OFF_X;
    float* xnb   = AR + OFF_XN;
    float* qb    = AR + OFF_QB;
    float* kvb   = AR + OFF_KV;
    float* ob    = AR + OFF_OB;
    float* scoreb = AR + OFF_SCORE;
    float* catb  = AR + OFF_CAT;

    auto run_mamba = [&](const float* X, int Lm, int i, float* OUT, const float* addend) {
        int Mrows = BATCH_ * Lm;
        gemm(X, DIMM, m_in_w + (size_t)i * 2 * DI_ * DIMM, DIMM,
             nullptr, nullptr, 0, xzb, 2 * DI_, Mrows, 2 * DI_, DIMM, 0);
        conv_kernel<<<(BATCH_ * Lm * DI_ + 255) / 256, 256>>>(
            xzb, m_conv_w + (size_t)i * DI_ * DC_, m_conv_b + (size_t)i * DI_, xcb, Lm);
        gemm(xcb, DI_, m_xproj_w + (size_t)i * 80 * DI_, DI_,
             nullptr, nullptr, 0, dblb, 80, Mrows, 80, DI_, 0);
        gemm(dblb, 80, m_dt_w + (size_t)i * DI_ * DTR_, DTR_,
             m_dt_b + (size_t)i * DI_, nullptr, 0, dtb, DI_, Mrows, DI_, DTR_, 1);
        scan_kernel<<<(BATCH_ * DI_ * DS_) / 256, 256>>>(
            dtb, dblb, xcb, xzb, m_A_log + (size_t)i * DI_ * DS_,
            m_D + (size_t)i * DI_, ysb, Lm);
        gemm(ysb, DI_, m_out_w + (size_t)i * DIMM * DI_, DI_,
             nullptr, addend, DIMM, OUT, DIMM, Mrows, DIMM, DI_, 0);
    };

    // ---- Stage A ----
    gemm(img_emb, DIN_, vproj_w, DIN_, vproj_b, nullptr, 0,
         feats, DIMM, BATCH_ * LSEQ_, DIMM, DIN_, 0);
    ln_kernel<<<BATCH_ * LSEQ_, 256>>>(feats, lnv_g, lnv_b, feats);

    // ---- Stage B ----
    run_mamba(feats, LSEQ_, 0, fwd, nullptr);
    flip_kernel<<<(BATCH_ * LSEQ_ * DIMM + 255) / 256, 256>>>(feats, flip, LSEQ_);
    run_mamba(flip, LSEQ_, 1, mo, nullptr);
    add3_kernel<<<(BATCH_ * LSEQ_ * DIMM + 255) / 256, 256>>>(fwd, mo, feats, cbuf, LSEQ_);

    // ---- Stage C ----
    bcast_kernel<<<(BATCH_ * NQ_ * DIMM + 255) / 256, 256>>>(queries, xb);

    for (int l = 0; l < NB_; l++) {
        ln_kernel<<<BATCH_ * NQ_, 256>>>(xb, sn_g + (size_t)l * DIMM, sn_b + (size_t)l * DIMM, xnb);
        run_mamba(xnb, NQ_, l + 2, xb, xnb);

        const float* wq = at_in_w + (size_t)l * 3 * DIMM * DIMM;
        const float* wkv = wq + (size_t)DIMM * DIMM;
        const float* bq = at_in_b + (size_t)l * 3 * DIMM;
        const float* bkv = bq + DIMM;

        gemm(xb, DIMM, wq, DIMM, bq, nullptr, 0, qb, DIMM, BATCH_ * NQ_, DIMM, DIMM, 0);
        gemm(cbuf, DIMM, wkv, DIMM, bkv, nullptr, 0, kvb, 2 * DIMM,
             BATCH_ * LSEQ_, 2 * DIMM, DIMM, 0);

        attn_kernel<<<(BATCH_ * NQ_ * NH_ + 127) / 128, 128>>>(qb, kvb, ob);

        gemm(ob, DIMM, at_out_w + (size_t)l * DIMM * DIMM, DIMM,
             at_out_b + (size_t)l * DIMM, nullptr, 0, scoreb, DIMM, BATCH_ * NQ_, DIMM, DIMM, 0);
        concat_kernel<<<(BATCH_ * NQ_ * 2 * DIMM + 255) / 256, 256>>>(xb, scoreb, catb);
        gemm(catb, 2 * DIMM, cr_w + (size_t)l * DIMM * 2 * DIMM, 2 * DIMM,
             cr_b + (size_t)l * DIMM, nullptr, 0, xb, DIMM, BATCH_ * NQ_, DIMM, 2 * DIMM, 0);
    }

    copy_kernel<<<(out_size + 255) / 256, 256>>>(xb, (float*)d_out, out_size);
}

// round 4
// speedup vs baseline: 2.7089x; 1.3971x over previous
#include <cuda_runtime.h>
#include <cuda_bf16.h>
#include <math.h>
#include <stdint.h>

#define DIMM 768
#define DIN_ 1024
#define NQ_ 384
#define NB_ 12
#define BATCH_ 2
#define LSEQ_ 1024
#define DI_ 1536
#define DS_ 16
#define DC_ 4
#define DTR_ 48
#define NH_ 16
#define HD_ 48
#define NM_ 14

// ---------------- arena (sizes in floats) ----------------
#define SZ_BL_DIM   (BATCH_*LSEQ_*DIMM)
#define SZ_XZ       (BATCH_*LSEQ_*2*DI_)
#define SZ_XC       (BATCH_*LSEQ_*DI_)
#define SZ_DBL      (BATCH_*LSEQ_*80)
#define SZ_Q_DIM    (BATCH_*NQ_*DIMM)
#define SZ_CAT      (BATCH_*NQ_*2*DIMM)
#define SZ_KVW      (NB_*2*DIMM*DIMM)          // 14155776
#define SZ_KVB      (NB_*2*DIMM)
#define SZ_KVALL    (BATCH_*LSEQ_*NB_*2*DIMM)  // 37748736
#define SZ_PART     (8*1024*1024)

#define OFF_FEATS  ((size_t)0)
#define OFF_FWD    (OFF_FEATS + SZ_BL_DIM)
#define OFF_FLIP   (OFF_FWD   + SZ_BL_DIM)
#define OFF_C      (OFF_FLIP  + SZ_BL_DIM)
#define OFF_MO     (OFF_C     + SZ_BL_DIM)
#define OFF_XZ     (OFF_MO    + SZ_BL_DIM)
#define OFF_XCB    (OFF_XZ    + SZ_XZ)
#define OFF_DBL    (OFF_XCB   + SZ_XC)
#define OFF_DT     (OFF_DBL   + SZ_DBL)
#define OFF_YS     (OFF_DT    + SZ_XC)
#define OFF_X      (OFF_YS    + SZ_XC)
#define OFF_XN     (OFF_X     + SZ_Q_DIM)
#define OFF_QB     (OFF_XN    + SZ_Q_DIM)
#define OFF_OB     (OFF_QB    + SZ_Q_DIM)
#define OFF_CAT    (OFF_OB    + SZ_Q_DIM)
#define OFF_KVW    (OFF_CAT   + SZ_CAT)
#define OFF_KVB    (OFF_KVW   + SZ_KVW)
#define OFF_KVALL  (OFF_KVB   + SZ_KVB)
#define OFF_PART   (OFF_KVALL + SZ_KVALL)
#define ARENA_SZ   (OFF_PART  + SZ_PART)

__device__ __align__(256) float g_arena[ARENA_SZ];

// ---------------- helpers ----------------
__device__ __forceinline__ float softplusf(float x) {
    return fmaxf(x, 0.f) + log1pf(expf(-fabsf(x)));
}
__device__ __forceinline__ float siluf(float x) {
    return x / (1.f + expf(-x));
}
// two floats -> packed bf16x2 hi + packed bf16x2 lo (split: x = hi + lo)
__device__ __forceinline__ void cvt2(float x, float y, uint32_t& hi, uint32_t& lo) {
    __nv_bfloat162 h2 = __floats2bfloat162_rn(x, y);
    float hx = __bfloat162float(__low2bfloat16(h2));
    float hy = __bfloat162float(__high2bfloat16(h2));
    __nv_bfloat162 l2 = __floats2bfloat162_rn(x - hx, y - hy);
    hi = *reinterpret_cast<uint32_t*>(&h2);
    lo = *reinterpret_cast<uint32_t*>(&l2);
}

#define MMA_BF16(d, a, b0, b1) \
    asm volatile("mma.sync.aligned.m16n8k16.row.col.f32.bf16.bf16.f32 " \
        "{%0,%1,%2,%3}, {%4,%5,%6,%7}, {%8,%9}, {%0,%1,%2,%3};" \
        : "+f"(d[0]), "+f"(d[1]), "+f"(d[2]), "+f"(d[3]) \
        : "r"(a[0]), "r"(a[1]), "r"(a[2]), "r"(a[3]), "r"(b0), "r"(b1))

// ================= bf16x2 tensor-core GEMM =================
// C = act(A @ B^T + bias) + addend. A:(M,K) lda, B:(N,K) ldb row-major.
// 128x128 tile, BK=32 (two k16 chunks), 256 thr, warps 4(M)x2(N), warp tile 32x64.
// smem: packed bf16x2 (kp = k/2), row stride PSTR uint32 (conflict-free).
#define PSTR 20
#define STG (128 * PSTR)
#define BF16_SMEM (2 * 4 * STG * 4)

__global__ __launch_bounds__(256, 2) void gemm_bf16x2_kernel(
    const float* __restrict__ A, int lda,
    const float* __restrict__ B, int ldb,
    const float* __restrict__ bias,
    const float* __restrict__ addend, int ldadd,
    float* __restrict__ C, int ldc, size_t zstride,
    int M, int N, int klen, int act)
{
    extern __shared__ uint32_t sm_[];
    int tid = threadIdx.x;
    int bm = blockIdx.y * 128, bn = blockIdx.x * 128;
    int kbeg = blockIdx.z * klen, kend = kbeg + klen;

    int lrow = tid & 127;
    int khalf = tid >> 7;                 // 0/1 : which 16-float k-half
    int arow = bm + lrow, brow = bn + lrow;
    bool avalid = arow < M, bvalid = brow < N;
    const float* Ap = A + (size_t)(avalid ? arow : 0) * lda;
    const float* Bp = B + (size_t)(bvalid ? brow : 0) * ldb;

    float4 stA[4], stB[4];

    auto gload = [&](int kbase) {
        int k0 = kbase + khalf * 16;
        const float4 z4 = make_float4(0.f, 0.f, 0.f, 0.f);
#pragma unroll
        for (int q = 0; q < 4; q++) {
            int k = k0 + q * 4;
            bool kin = k < kend;
            stA[q] = (avalid && kin) ? *(const float4*)(Ap + k) : z4;
            stB[q] = (bvalid && kin) ? *(const float4*)(Bp + k) : z4;
        }
    };

    auto ssave = [&](int p) {
        uint32_t* base = sm_ + (size_t)p * 4 * STG;
        uint32_t* ah = base;
        uint32_t* al = base + STG;
        uint32_t* bh = base + 2 * STG;
        uint32_t* bl = base + 3 * STG;
        int col0 = khalf * 8;
#pragma unroll
        for (int qq = 0; qq < 2; qq++) {
            uint4 h4, l4;
            cvt2(stA[2*qq].x,   stA[2*qq].y,   h4.x, l4.x);
            cvt2(stA[2*qq].z,   stA[2*qq].w,   h4.y, l4.y);
            cvt2(stA[2*qq+1].x, stA[2*qq+1].y, h4.z, l4.z);
            cvt2(stA[2*qq+1].z, stA[2*qq+1].w, h4.w, l4.w);
            *(uint4*)&ah[lrow * PSTR + col0 + qq * 4] = h4;
            *(uint4*)&al[lrow * PSTR + col0 + qq * 4] = l4;
            cvt2(stB[2*qq].x,   stB[2*qq].y,   h4.x, l4.x);
            cvt2(stB[2*qq].z,   stB[2*qq].w,   h4.y, l4.y);
            cvt2(stB[2*qq+1].x, stB[2*qq+1].y, h4.z, l4.z);
            cvt2(stB[2*qq+1].z, stB[2*qq+1].w, h4.w, l4.w);
            *(uint4*)&bh[lrow * PSTR + col0 + qq * 4] = h4;
            *(uint4*)&bl[lrow * PSTR + col0 + qq * 4] = l4;
        }
    };

    gload(kbeg);
    ssave(0);
    __syncthreads();

    int lane = tid & 31, warp = tid >> 5;
    int wm = warp & 3, wn = warp >> 2;
    int m0 = wm * 32, n0 = wn * 64;
    int lr = lane >> 2, lc = lane & 3;

    float acc[2][8][4];
#pragma unroll
    for (int mi = 0; mi < 2; mi++)
#pragma unroll
        for (int ni = 0; ni < 8; ni++)
#pragma unroll
            for (int r = 0; r < 4; r++) acc[mi][ni][r] = 0.f;

    int p = 0;
    int nsteps = (klen + 31) / 32;
    for (int step = 0; step < nsteps; step++) {
        bool more = (step + 1 < nsteps);
        if (more) gload(kbeg + (step + 1) * 32);

        const uint32_t* base = sm_ + (size_t)p * 4 * STG;
        const uint32_t* ah = base;
        const uint32_t* al = base + STG;
        const uint32_t* bh = base + 2 * STG;
        const uint32_t* bl = base + 3 * STG;
#pragma unroll
        for (int c = 0; c < 2; c++) {
            int kb = c * 8;
            uint32_t afh[2][4], afl[2][4];
#pragma unroll
            for (int mi = 0; mi < 2; mi++) {
                int r0 = m0 + mi * 16 + lr;
                afh[mi][0] = ah[r0 * PSTR + kb + lc];
                afh[mi][1] = ah[(r0 + 8) * PSTR + kb + lc];
                afh[mi][2] = ah[r0 * PSTR + kb + lc + 4];
                afh[mi][3] = ah[(r0 + 8) * PSTR + kb + lc + 4];
                afl[mi][0] = al[r0 * PSTR + kb + lc];
                afl[mi][1] = al[(r0 + 8) * PSTR + kb + lc];
                afl[mi][2] = al[r0 * PSTR + kb + lc + 4];
                afl[mi][3] = al[(r0 + 8) * PSTR + kb + lc + 4];
            }
#pragma unroll
            for (int ni = 0; ni < 8; ni++) {
                int nb = (n0 + ni * 8 + lr) * PSTR + kb;
                uint32_t b0h = bh[nb + lc], b1h = bh[nb + lc + 4];
                uint32_t b0l = bl[nb + lc], b1l = bl[nb + lc + 4];
#pragma unroll
                for (int mi = 0; mi < 2; mi++) {
                    MMA_BF16(acc[mi][ni], afh[mi], b0h, b1h);
                    MMA_BF16(acc[mi][ni], afh[mi], b0l, b1l);
                    MMA_BF16(acc[mi][ni], afl[mi], b0h, b1h);
                }
            }
        }
        if (more) {
            ssave(p ^ 1);
            __syncthreads();
            p ^= 1;
        }
    }

    // ---- epilogue ----
    float* Cz = C + (size_t)blockIdx.z * zstride;
#pragma unroll
    for (int mi = 0; mi < 2; mi++) {
#pragma unroll
        for (int rh = 0; rh < 2; rh++) {
            int m = bm + m0 + mi * 16 + lr + rh * 8;
            if (m >= M) continue;
#pragma unroll
            for (int ni = 0; ni < 8; ni++) {
#pragma unroll
                for (int cc = 0; cc < 2; cc++) {
                    int n = bn + n0 + ni * 8 + 2 * lc + cc;
                    if (n >= N) continue;
                    float v = acc[mi][ni][rh * 2 + cc];
                    if (bias) v += bias[n];
                    if (act == 1) v = softplusf(v);
                    if (addend) v += addend[(size_t)m * ldadd + n];
                    Cz[(size_t)m * ldc + n] = v;
                }
            }
        }
    }
}

// ============ split-K reduce with epilogue ============
__global__ void reduce_kernel(const float* __restrict__ part, size_t pstride, int nsplit,
                              const float* __restrict__ bias,
                              const float* __restrict__ addend, int ldadd,
                              float* __restrict__ C, int ldc, int M, int N, int act)
{
    int idx = blockIdx.x * blockDim.x + threadIdx.x;
    if (idx >= M * N) return;
    int m = idx / N, n = idx % N;
    float v = 0.f;
    for (int z = 0; z < nsplit; z++) v += part[(size_t)z * pstride + idx];
    if (bias) v += bias[n];
    if (act == 1) v = softplusf(v);
    if (addend) v += addend[(size_t)m * ldadd + n];
    C[(size_t)m * ldc + n] = v;
}

static float* g_partial = nullptr;

static void gemm(const float* A, int lda, const float* B, int ldb,
                 const float* bias, const float* addend, int ldadd,
                 float* C, int ldc, int M, int N, int K, int act)
{
    int gm = (M + 127) / 128, gn = (N + 127) / 128;
    int split = 1;
    while (gm * gn * split < 132 && split < 8 &&
           (K % (split * 2)) == 0 && (K / (split * 2)) >= 48 &&
           ((K / (split * 2)) % 16) == 0) split *= 2;
    int klen = K / split;
    dim3 grid(gn, gm, split);
    if (split == 1) {
        gemm_bf16x2_kernel<<<grid, 256, BF16_SMEM>>>(
            A, lda, B, ldb, bias, addend, ldadd, C, ldc, 0, M, N, klen, act);
    } else {
        gemm_bf16x2_kernel<<<grid, 256, BF16_SMEM>>>(
            A, lda, B, ldb, nullptr, nullptr, 0,
            g_partial, N, (size_t)M * N, M, N, klen, 0);
        reduce_kernel<<<(M * N + 255) / 256, 256>>>(g_partial, (size_t)M * N, split,
                                                    bias, addend, ldadd, C, ldc, M, N, act);
    }
}

// ---------------- layernorm ----------------
__global__ void ln_kernel(const float* __restrict__ x, const float* __restrict__ g,
                          const float* __restrict__ b, float* __restrict__ y)
{
    int r = blockIdx.x;
    const float* xp = x + (size_t)r * DIMM;
    float s = 0.f, ss = 0.f;
    for (int i = threadIdx.x; i < DIMM; i += blockDim.x) {
        float v = xp[i]; s += v; ss += v * v;
    }
    __shared__ float shs[8], shss[8];
    for (int o = 16; o > 0; o >>= 1) {
        s += __shfl_xor_sync(0xffffffffu, s, o);
        ss += __shfl_xor_sync(0xffffffffu, ss, o);
    }
    int w = threadIdx.x >> 5;
    if ((threadIdx.x & 31) == 0) { shs[w] = s; shss[w] = ss; }
    __syncthreads();
    if (threadIdx.x == 0) {
        float ts = 0.f, tss = 0.f;
        int nw = blockDim.x >> 5;
        for (int i = 0; i < nw; i++) { ts += shs[i]; tss += shss[i]; }
        shs[0] = ts; shss[0] = tss;
    }
    __syncthreads();
    float mean = shs[0] / (float)DIMM;
    float var = shss[0] / (float)DIMM - mean * mean;
    float inv = rsqrtf(var + 1e-5f);
    float* yp = y + (size_t)r * DIMM;
    for (int i = threadIdx.x; i < DIMM; i += blockDim.x)
        yp[i] = (xp[i] - mean) * inv * g[i] + b[i];
}

// ---------------- depthwise causal conv + silu ----------------
__global__ void conv_kernel(const float* __restrict__ xz, const float* __restrict__ cw,
                            const float* __restrict__ cb, float* __restrict__ xc, int L)
{
    int idx = blockIdx.x * blockDim.x + threadIdx.x;
    int total = BATCH_ * L * DI_;
    if (idx >= total) return;
    int d = idx % DI_;
    int l = (idx / DI_) % L;
    int b = idx / (DI_ * L);
    float sum = cb[d];
    const float* base = xz + ((size_t)b * L) * (2 * DI_) + d;
#pragma unroll
    for (int j = 0; j < DC_; j++) {
        int lt = l - (DC_ - 1) + j;
        if (lt >= 0) sum += base[(size_t)lt * (2 * DI_)] * cw[d * DC_ + j];
    }
    xc[idx] = siluf(sum);
}

// ---------------- selective scan (1-step software pipeline) ----------------
__global__ void scan_kernel(const float* __restrict__ dt, const float* __restrict__ dbl,
                            const float* __restrict__ xc, const float* __restrict__ xz,
                            const float* __restrict__ A_log, const float* __restrict__ Dp,
                            float* __restrict__ ys, int L)
{
    int idx = blockIdx.x * blockDim.x + threadIdx.x;
    int s = idx & 15;
    int bd = idx >> 4;
    int d = bd % DI_;
    int b = bd / DI_;
    float Av = -__expf(A_log[d * DS_ + s]);
    float Dv = Dp[d];
    float h = 0.f;
    const float* dt_p = dt + (size_t)b * L * DI_ + d;
    const float* xc_p = xc + (size_t)b * L * DI_ + d;
    const float* z_p = xz + (size_t)b * L * (2 * DI_) + DI_ + d;
    const float* bl_p = dbl + (size_t)b * L * 80;
    float* ys_p = ys + (size_t)b * L * DI_ + d;

    float dtv = dt_p[0];
    float xcv = xc_p[0];
    float Bv = bl_p[48 + s];
    float Cv = bl_p[64 + s];
    float zv = (s == 0) ? z_p[0] : 0.f;

    for (int t = 0; t < L; t++) {
        float dtn = 0.f, xcn = 0.f, Bn = 0.f, Cn = 0.f, zn = 0.f;
        if (t + 1 < L) {
            size_t t1 = t + 1;
            dtn = dt_p[t1 * DI_];
            xcn = xc_p[t1 * DI_];
            Bn = bl_p[t1 * 80 + 48 + s];
            Cn = bl_p[t1 * 80 + 64 + s];
            if (s == 0) zn = z_p[t1 * (2 * DI_)];
        }
        h = __expf(dtv * Av) * h + dtv * Bv * xcv;
        float pr = h * Cv;
        pr += __shfl_xor_sync(0xffffffffu, pr, 8);
        pr += __shfl_xor_sync(0xffffffffu, pr, 4);
        pr += __shfl_xor_sync(0xffffffffu, pr, 2);
        pr += __shfl_xor_sync(0xffffffffu, pr, 1);
        if (s == 0) {
            float y = pr + Dv * xcv;
            ys_p[(size_t)t * DI_] = y * siluf(zv);
        }
        dtv = dtn; xcv = xcn; Bv = Bn; Cv = Cn; zv = zn;
    }
}

// ---------------- local cross-attention (batched kv buffer) ----------------
__global__ void attn_kernel(const float* __restrict__ q, const float* __restrict__ kv,
                            float* __restrict__ o, int ldkv, int loff)
{
    int idx = blockIdx.x * blockDim.x + threadIdx.x;
    if (idx >= BATCH_ * NQ_ * NH_) return;
    int h = idx % NH_;
    int qi = (idx / NH_) % NQ_;
    int b = idx / (NH_ * NQ_);
    const int kpq = LSEQ_ / NQ_;
    const int extra = LSEQ_ % NQ_;
    int start = qi * kpq + (qi < extra ? qi : extra);
    int cnt = kpq + (qi < extra ? 1 : 0);
    const float* qp = q + ((size_t)(b * NQ_ + qi)) * DIMM + h * HD_;
    float s[3];
    float mx = -1e30f;
    for (int j = 0; j < cnt; j++) {
        const float* kp = kv + ((size_t)(b * LSEQ_ + start + j)) * ldkv + loff + h * HD_;
        float dot = 0.f;
#pragma unroll
        for (int d = 0; d < HD_; d++) dot += qp[d] * kp[d];
        dot *= 0.14433756729740643f;
        s[j] = dot;
        if (dot > mx) mx = dot;
    }
    float sum = 0.f;
    for (int j = 0; j < cnt; j++) { s[j] = expf(s[j] - mx); sum += s[j]; }
    float inv = 1.f / sum;
    float* op = o + ((size_t)(b * NQ_ + qi)) * DIMM + h * HD_;
    for (int d = 0; d < HD_; d++) {
        float acc = 0.f;
        for (int j = 0; j < cnt; j++)
            acc += s[j] * kv[((size_t)(b * LSEQ_ + start + j)) * ldkv + loff + DIMM + h * HD_ + d];
        op[d] = acc * inv;
    }
}

// ---------------- kv weight/bias gather (12 layers -> contiguous) ----------------
__global__ void kvgather_w(const float* __restrict__ w, float* __restrict__ out)
{
    int idx = blockIdx.x * blockDim.x + threadIdx.x;
    int total = NB_ * 2 * DIMM * DIMM;
    if (idx >= total) return;
    int n = idx / DIMM, k = idx % DIMM;
    int l = n / (2 * DIMM), r = n % (2 * DIMM);
    out[idx] = w[((size_t)l * 3 * DIMM + DIMM + r) * DIMM + k];
}
__global__ void kvgather_b(const float* __restrict__ b, float* __restrict__ out)
{
    int n = blockIdx.x * blockDim.x + threadIdx.x;
    if (n >= NB_ * 2 * DIMM) return;
    int l = n / (2 * DIMM), r = n % (2 * DIMM);
    out[n] = b[(size_t)l * 3 * DIMM + DIMM + r];
}

// ---------------- elementwise utilities ----------------
__global__ void flip_kernel(const float* __restrict__ in, float* __restrict__ out, int L)
{
    int idx = blockIdx.x * blockDim.x + threadIdx.x;
    int total = BATCH_ * L * DIMM;
    if (idx >= total) return;
    int d = idx % DIMM;
    int l = (idx / DIMM) % L;
    int b = idx / (DIMM * L);
    out[idx] = in[((size_t)b * L + (L - 1 - l)) * DIMM + d];
}

__global__ void add3_kernel(const float* __restrict__ fwd, const float* __restrict__ mo,
                            const float* __restrict__ feats, float* __restrict__ c, int L)
{
    int idx = blockIdx.x * blockDim.x + threadIdx.x;
    int total = BATCH_ * L * DIMM;
    if (idx >= total) return;
    int d = idx % DIMM;
    int l = (idx / DIMM) % L;
    int b = idx / (DIMM * L);
    c[idx] = fwd[idx] + mo[((size_t)b * L + (L - 1 - l)) * DIMM + d] + feats[idx];
}

__global__ void bcast_kernel(const float* __restrict__ queries, float* __restrict__ x)
{
    int idx = blockIdx.x * blockDim.x + threadIdx.x;
    int total = BATCH_ * NQ_ * DIMM;
    if (idx >= total) return;
    x[idx] = queries[idx % (NQ_ * DIMM)];
}

__global__ void copy_kernel(const float* __restrict__ a, float* __restrict__ b, int n)
{
    int idx = blockIdx.x * blockDim.x + threadIdx.x;
    if (idx < n) b[idx] = a[idx];
}

// ---------------- host orchestration ----------------
extern "C" void kernel_launch(void* const* d_in, const int* in_sizes, int n_in,
                              void* d_out, int out_size)
{
    (void)in_sizes; (void)n_in;
    const float* img_emb   = (const float*)d_in[0];
    const float* queries   = (const float*)d_in[1];
    const float* vproj_w   = (const float*)d_in[2];
    const float* vproj_b   = (const float*)d_in[3];
    const float* lnv_g     = (const float*)d_in[4];
    const float* lnv_b     = (const float*)d_in[5];
    const float* m_in_w    = (const float*)d_in[6];
    const float* m_conv_w  = (const float*)d_in[7];
    const float* m_conv_b  = (const float*)d_in[8];
    const float* m_xproj_w = (const float*)d_in[9];
    const float* m_dt_w    = (const float*)d_in[10];
    const float* m_dt_b    = (const float*)d_in[11];
    const float* m_A_log   = (const float*)d_in[12];
    const float* m_D       = (const float*)d_in[13];
    const float* m_out_w   = (const float*)d_in[14];
    const float* sn_g      = (const float*)d_in[15];
    const float* sn_b      = (const float*)d_in[16];
    const float* at_in_w   = (const float*)d_in[17];
    const float* at_in_b   = (const float*)d_in[18];
    const float* at_out_w  = (const float*)d_in[19];
    const float* at_out_b  = (const float*)d_in[20];
    const float* cr_w      = (const float*)d_in[21];
    const float* cr_b      = (const float*)d_in[22];

    cudaFuncSetAttribute(gemm_bf16x2_kernel,
                         cudaFuncAttributeMaxDynamicSharedMemorySize, BF16_SMEM);

    float* AR = nullptr;
    cudaGetSymbolAddress((void**)&AR, g_arena);
    g_partial = AR + OFF_PART;

    float* feats = AR + OFF_FEATS;
    float* fwd   = AR + OFF_FWD;
    float* flip  = AR + OFF_FLIP;
    float* cbuf  = AR + OFF_C;
    float* mo    = AR + OFF_MO;
    float* xzb   = AR + OFF_XZ;
    float* xcb   = AR + OFF_XCB;
    float* dblb  = AR + OFF_DBL;
    float* dtb   = AR + OFF_DT;
    float* ysb   = AR + OFF_YS;
    float* xb    = AR + OFF_X;
    float* xnb   = AR + OFF_XN;
    float* qb    = AR + OFF_QB;
    float* ob    = AR + OFF_OB;
    float* catb  = AR + OFF_CAT;
    float* kvw   = AR + OFF_KVW;
    float* kvbias = AR + OFF_KVB;
    float* kvall = AR + OFF_KVALL;

    // run_mamba: OUT has row stride ldout; optional addend (stride DIMM)
    auto run_mamba = [&](const float* X, int ldx, int Lm, int i,
                         float* OUT, int ldout, const float* addend) {
        int Mrows = BATCH_ * Lm;
        gemm(X, ldx, m_in_w + (size_t)i * 2 * DI_ * DIMM, DIMM,
             nullptr, nullptr, 0, xzb, 2 * DI_, Mrows, 2 * DI_, DIMM, 0);
        conv_kernel<<<(BATCH_ * Lm * DI_ + 255) / 256, 256>>>(
            xzb, m_conv_w + (size_t)i * DI_ * DC_, m_conv_b + (size_t)i * DI_, xcb, Lm);
        gemm(xcb, DI_, m_xproj_w + (size_t)i * 80 * DI_, DI_,
             nullptr, nullptr, 0, dblb, 80, Mrows, 80, DI_, 0);
        gemm(dblb, 80, m_dt_w + (size_t)i * DI_ * DTR_, DTR_,
             m_dt_b + (size_t)i * DI_, nullptr, 0, dtb, DI_, Mrows, DI_, DTR_, 1);
        scan_kernel<<<(BATCH_ * DI_ * DS_) / 256, 256>>>(
            dtb, dblb, xcb, xzb, m_A_log + (size_t)i * DI_ * DS_,
            m_D + (size_t)i * DI_, ysb, Lm);
        gemm(ysb, DI_, m_out_w + (size_t)i * DIMM * DI_, DI_,
             nullptr, addend, DIMM, OUT, ldout, Mrows, DIMM, DI_, 0);
    };

    // ---- Stage A ----
    gemm(img_emb, DIN_, vproj_w, DIN_, vproj_b, nullptr, 0,
         feats, DIMM, BATCH_ * LSEQ_, DIMM, DIN_, 0);
    ln_kernel<<<BATCH_ * LSEQ_, 256>>>(feats, lnv_g, lnv_b, feats);

    // ---- Stage B ----
    run_mamba(feats, DIMM, LSEQ_, 0, fwd, DIMM, nullptr);
    flip_kernel<<<(BATCH_ * LSEQ_ * DIMM + 255) / 256, 256>>>(feats, flip, LSEQ_);
    run_mamba(flip, DIMM, LSEQ_, 1, mo, DIMM, nullptr);
    add3_kernel<<<(BATCH_ * LSEQ_ * DIMM + 255) / 256, 256>>>(fwd, mo, feats, cbuf, LSEQ_);

    // ---- Batched KV for all 12 blocks ----
    kvgather_w<<<(NB_ * 2 * DIMM * DIMM + 255) / 256, 256>>>(at_in_w, kvw);
    kvgather_b<<<(NB_ * 2 * DIMM + 255) / 256, 256>>>(at_in_b, kvbias);
    gemm(cbuf, DIMM, kvw, DIMM, kvbias, nullptr, 0,
         kvall, NB_ * 2 * DIMM, BATCH_ * LSEQ_, NB_ * 2 * DIMM, DIMM, 0);

    // ---- Stage C ----
    bcast_kernel<<<(BATCH_ * NQ_ * DIMM + 255) / 256, 256>>>(queries, xb);

    for (int l = 0; l < NB_; l++) {
        ln_kernel<<<BATCH_ * NQ_, 256>>>(xb, sn_g + (size_t)l * DIMM, sn_b + (size_t)l * DIMM, xnb);
        // x_mid = mamba(xn)+xn written into catb[:, :768] (row stride 1536)
        run_mamba(xnb, DIMM, NQ_, l + 2, catb, 2 * DIMM, xnb);

        const float* wq = at_in_w + (size_t)l * 3 * DIMM * DIMM;
        const float* bq = at_in_b + (size_t)l * 3 * DIMM;
        gemm(catb, 2 * DIMM, wq, DIMM, bq, nullptr, 0, qb, DIMM, BATCH_ * NQ_, DIMM, DIMM, 0);

        attn_kernel<<<(BATCH_ * NQ_ * NH_ + 127) / 128, 128>>>(
            qb, kvall, ob, NB_ * 2 * DIMM, l * 2 * DIMM);

        // score written into catb[:, 768:] (row stride 1536)
        gemm(ob, DIMM, at_out_w + (size_t)l * DIMM * DIMM, DIMM,
             at_out_b + (size_t)l * DIMM, nullptr, 0, catb + DIMM, 2 * DIMM,
             BATCH_ * NQ_, DIMM, DIMM, 0);

        // x = [x_mid, score] @ cross_w.T + cross_b
        gemm(catb, 2 * DIMM, cr_w + (size_t)l * DIMM * 2 * DIMM, 2 * DIMM,
             cr_b + (size_t)l * DIMM, nullptr, 0, xb, DIMM, BATCH_ * NQ_, DIMM, 2 * DIMM, 0);
    }

    copy_kernel<<<(out_size + 255) / 256, 256>>>(xb, (float*)d_out, out_size);
}